// round 6
// baseline (speedup 1.0000x reference)
#include <cuda_runtime.h>
#include <cuda_bf16.h>
#include <cstdint>
#include <math.h>

#define B_DIM 4
#define S_DIM 2048
#define T_DIM 256
#define H_DIM 2048
#define NHEAD 16
#define HD_DIM 128

#define BK 16
#define NSTAGE 3
#define STAGE_PITCH 68       // fp32 epilogue staging pitch

// ---------------------------------------------------------------------------
// Persistent scratch (device globals)
// ---------------------------------------------------------------------------
__device__ __nv_bfloat16 g_hsh[8192*2048], g_hsl[8192*2048];
__device__ __nv_bfloat16 g_ath[1024*2048], g_atl[1024*2048];
__device__ __nv_bfloat16 g_Wqh[2048*2048], g_Wql[2048*2048];
__device__ __nv_bfloat16 g_Wkh[2048*2048], g_Wkl[2048*2048];
__device__ __nv_bfloat16 g_Wvh[2048*2048], g_Wvl[2048*2048];
__device__ __nv_bfloat16 g_Woh[2048*2048], g_Wol[2048*2048];
__device__ __nv_bfloat16 g_Qh[8192*2048],  g_Ql[8192*2048];
__device__ __nv_bfloat16 g_Kh[1024*2048],  g_Kl[1024*2048];
__device__ __nv_bfloat16 g_Vth[64*128*256], g_Vtl[64*128*256];
__device__ float         g_S[64u*2048u*256u];
__device__ __nv_bfloat16 g_Ph[64u*2048u*256u], g_Pl[64u*2048u*256u];
__device__ __nv_bfloat16 g_Ch[8192*2048],  g_Cl[8192*2048];
__device__ float         g_D[8192*2048];

// ---------------------------------------------------------------------------
// Helpers
// ---------------------------------------------------------------------------
__device__ __forceinline__ uint32_t smem_to_u32(const void* p) {
    uint32_t a;
    asm("{ .reg .u64 t; cvta.to.shared.u64 t, %1; cvt.u32.u64 %0, t; }" : "=r"(a) : "l"(p));
    return a;
}
__device__ __forceinline__ void cp16(uint32_t dst, const void* src) {
    asm volatile("cp.async.cg.shared.global [%0], [%1], 16;" :: "r"(dst), "l"(src));
}
#define CP_COMMIT() asm volatile("cp.async.commit_group;")
#define CP_WAIT1()  asm volatile("cp.async.wait_group 1;")

__device__ __forceinline__ void ldmx4(uint32_t* r, uint32_t addr) {
    asm volatile("ldmatrix.sync.aligned.m8n8.x4.shared.b16 {%0,%1,%2,%3}, [%4];"
                 : "=r"(r[0]), "=r"(r[1]), "=r"(r[2]), "=r"(r[3]) : "r"(addr));
}
__device__ __forceinline__ void mma16816(float* c, const uint32_t* a, const uint32_t* b) {
    asm volatile("mma.sync.aligned.m16n8k16.row.col.f32.bf16.bf16.f32 "
                 "{%0,%1,%2,%3}, {%4,%5,%6,%7}, {%8,%9}, {%0,%1,%2,%3};"
                 : "+f"(c[0]), "+f"(c[1]), "+f"(c[2]), "+f"(c[3])
                 : "r"(a[0]), "r"(a[1]), "r"(a[2]), "r"(a[3]), "r"(b[0]), "r"(b[1]));
}
__device__ __forceinline__ void split_pair(float x0, float x1, uint32_t& hi, uint32_t& lo) {
    __nv_bfloat162 h = __floats2bfloat162_rn(x0, x1);
    float r0 = x0 - __bfloat162float(h.x);
    float r1 = x1 - __bfloat162float(h.y);
    __nv_bfloat162 l = __floats2bfloat162_rn(r0, r1);
    hi = *(uint32_t*)&h;
    lo = *(uint32_t*)&l;
}
// XOR-swizzled offset inside a (rows x 16 bf16) tile with 128-row subtiles
__device__ __forceinline__ uint32_t swz(int row, int seg) {
    return (row >> 7) * 4096 + (row & 127) * 32 + ((seg << 4) ^ ((row & 4) << 2));
}

// ---------------------------------------------------------------------------
// Pre-pass: split fp32 -> bf16 hi/lo
// ---------------------------------------------------------------------------
__global__ void split_kernel(const float* __restrict__ in,
                             __nv_bfloat16* __restrict__ hi,
                             __nv_bfloat16* __restrict__ lo)
{
    int idx = blockIdx.x * blockDim.x + threadIdx.x;
    float4 v = ((const float4*)in)[idx];
    uint32_t h0, l0, h1, l1;
    split_pair(v.x, v.y, h0, l0);
    split_pair(v.z, v.w, h1, l1);
    ((uint2*)hi)[idx] = make_uint2(h0, h1);
    ((uint2*)lo)[idx] = make_uint2(l0, l1);
}

// ---------------------------------------------------------------------------
// Tensor-core GEMM: C = A[M,K] * B[N,K]^T, pre-split bf16 hi/lo, 3-pass MMA
// CTA tile 128 x BN (BN = 128 or 256), warp tile 64 x BN/4, 8 warps (2x4)
//   MODE 0: proj+bias -> hi/lo out     MODE 1: V-proj -> Vt hi/lo scatter
//   MODE 2: scores -> fp32 (scale/clip/mask)
//   MODE 3: PV -> ctx hi/lo scatter    MODE 4: proj+bias -> fp32
// ---------------------------------------------------------------------------
template<int MODE, int BN>
__global__ void __launch_bounds__(256, 1)
mma_gemm(const __nv_bfloat16* __restrict__ Ah, const __nv_bfloat16* __restrict__ Al,
         const __nv_bfloat16* __restrict__ Bh, const __nv_bfloat16* __restrict__ Bl,
         const float* __restrict__ bias, const int* __restrict__ mask,
         float* __restrict__ Cf, __nv_bfloat16* __restrict__ Ch,
         __nv_bfloat16* __restrict__ Cl, int K, int lda, int ldb, int ldc)
{
    extern __shared__ __align__(16) char smem[];
    constexpr int WN  = BN / 4;          // warp n width
    constexpr int NF  = WN / 8;          // 8-col frags per warp
    constexpr int NP  = NF / 2;          // ldmx4 pairs on B
    constexpr int ATB = 4096;            // A hi tile bytes (128x16 bf16)
    constexpr int BTB = BN * 32;         // B hi tile bytes
    constexpr int STAGE = 2 * (ATB + BTB);
    constexpr int NPASS = BN / 64;

    const int tid = threadIdx.x;
    const int wid = tid >> 5;
    const int lane = tid & 31;
    const int g = lane >> 2, ti = lane & 3;
    const int mwb = (wid >> 2) * 64;
    const int nwb = (wid & 3) * WN;
    const uint32_t sbase = smem_to_u32(smem);

    const int m0 = blockIdx.y * 128;
    const int n0 = blockIdx.x * BN;
    int bb = 0, hh = 0;
    size_t aoff = 0, boff = 0;
    if (MODE == 2) {
        bb = blockIdx.z >> 4; hh = blockIdx.z & 15;
        aoff = (size_t)bb * S_DIM * H_DIM + hh * HD_DIM;
        boff = (size_t)bb * T_DIM * H_DIM + hh * HD_DIM;
    }
    if (MODE == 3) {
        bb = blockIdx.z >> 4; hh = blockIdx.z & 15;
        aoff = (size_t)blockIdx.z * S_DIM * T_DIM;
        boff = (size_t)blockIdx.z * HD_DIM * T_DIM;
    }
    const __nv_bfloat16* pAh = Ah + aoff;
    const __nv_bfloat16* pAl = Al + aoff;
    const __nv_bfloat16* pBh = Bh + boff;
    const __nv_bfloat16* pBl = Bl + boff;

    // cp.async mapping
    const int crow = tid >> 1;
    const int cseg = tid & 1;
    const size_t asrc = (size_t)(m0 + crow) * lda + cseg * 8;
    const uint32_t adst = swz(crow, cseg);

    const int nchunk = K / BK;

    auto issue = [&](int c) {
        const uint32_t st = sbase + (c % NSTAGE) * STAGE;
        const int kt = c * BK;
        cp16(st + adst,       pAh + asrc + kt);
        cp16(st + ATB + adst, pAl + asrc + kt);
#pragma unroll
        for (int j = 0; j < BN / 128; j++) {
            const int row = crow + 128 * j;
            const size_t bsrc = (size_t)(n0 + row) * ldb + cseg * 8 + kt;
            const uint32_t bdst = swz(row, cseg);
            cp16(st + 2*ATB + bdst,       pBh + bsrc);
            cp16(st + 2*ATB + BTB + bdst, pBl + bsrc);
        }
    };

    float acc[4][NF][4];
#pragma unroll
    for (int i = 0; i < 4; i++)
#pragma unroll
        for (int j = 0; j < NF; j++)
#pragma unroll
            for (int q = 0; q < 4; q++) acc[i][j][q] = 0.f;

    issue(0); CP_COMMIT();
    issue(1); CP_COMMIT();

    const int arow = lane & 15;
    const int aseg = lane >> 4;
    const int brow = (lane & 7) + ((lane >> 4) << 3);
    const int bseg = (lane >> 3) & 1;

    for (int c = 0; c < nchunk; c++) {
        CP_WAIT1();
        __syncthreads();
        if (c + 2 < nchunk) issue(c + 2);
        CP_COMMIT();

        const uint32_t sbuf = sbase + (c % NSTAGE) * STAGE;
        uint32_t ah[4][4], al[4][4];
#pragma unroll
        for (int mf = 0; mf < 4; mf++) {
            uint32_t ad = sbuf + swz(mwb + mf * 16 + arow, aseg);
            ldmx4(ah[mf], ad);
            ldmx4(al[mf], ad + ATB);
        }
#pragma unroll
        for (int np = 0; np < NP; np++) {
            uint32_t rh[4], rl[4];
            uint32_t bd = sbuf + 2*ATB + swz(nwb + np * 16 + brow, bseg);
            ldmx4(rh, bd);
            ldmx4(rl, bd + BTB);
#pragma unroll
            for (int mf = 0; mf < 4; mf++) {
                mma16816(acc[mf][2*np],   ah[mf], rh);
                mma16816(acc[mf][2*np+1], ah[mf], rh + 2);
                mma16816(acc[mf][2*np],   ah[mf], rl);
                mma16816(acc[mf][2*np+1], ah[mf], rl + 2);
                mma16816(acc[mf][2*np],   al[mf], rh);
                mma16816(acc[mf][2*np+1], al[mf], rh + 2);
            }
        }
        __syncthreads();
    }

    // Epilogue: NPASS passes of a 128x64 fp32 SMEM stage -> coalesced stores
    float* stage = (float*)smem;
    const int wp = nwb >> 6;             // which pass this warp writes
    const int cmb = (nwb & 63);
#pragma unroll
    for (int p = 0; p < NPASS; p++) {
        if (p) __syncthreads();
        if (wp == p) {
#pragma unroll
            for (int mf = 0; mf < 4; mf++)
#pragma unroll
                for (int nf = 0; nf < NF; nf++) {
                    const int row = mwb + mf * 16 + g;
                    const int cm = cmb + nf * 8 + ti * 2;
                    *(float2*)&stage[row * STAGE_PITCH + cm] =
                        make_float2(acc[mf][nf][0], acc[mf][nf][1]);
                    *(float2*)&stage[(row + 8) * STAGE_PITCH + cm] =
                        make_float2(acc[mf][nf][2], acc[mf][nf][3]);
                }
        }
        __syncthreads();
#pragma unroll
        for (int it = 0; it < 8; it++) {
            const int lin = it * 1024 + tid * 4;
            const int row = lin >> 6;
            const int cm = lin & 63;
            const int col = p * 64 + cm;
            float4 v = *(float4*)&stage[row * STAGE_PITCH + cm];
            if (MODE == 0 || MODE == 1 || MODE == 3) {
                float b0 = 0.f, b1 = 0.f, b2 = 0.f, b3 = 0.f;
                size_t off;
                if (MODE == 0) {
                    float4 b4 = *(const float4*)(bias + n0 + col);
                    b0 = b4.x; b1 = b4.y; b2 = b4.z; b3 = b4.w;
                    off = (size_t)(m0 + row) * ldc + n0 + col;
                } else if (MODE == 1) {
                    const int gr = m0 + row;             // feature = h*128+d
                    const int h = gr >> 7, d = gr & 127;
                    const int n = n0 + col;              // b*256+t
                    const int b = n >> 8, t = n & 255;
                    b0 = b1 = b2 = b3 = bias[gr];
                    off = ((size_t)(b * NHEAD + h) * HD_DIM + d) * T_DIM + t;
                } else {
                    off = (size_t)(bb * S_DIM + m0 + row) * H_DIM + hh * HD_DIM + col;
                }
                uint32_t h0, l0, h1, l1;
                split_pair(v.x + b0, v.y + b1, h0, l0);
                split_pair(v.z + b2, v.w + b3, h1, l1);
                *(uint2*)(Ch + off) = make_uint2(h0, h1);
                *(uint2*)(Cl + off) = make_uint2(l0, l1);
            } else if (MODE == 2) {
                const float invs = 0.08838834764831845f;  // 1/sqrt(128)
                float vv[4] = {v.x, v.y, v.z, v.w};
                float4 o; float* po = &o.x;
                const int mb = bb * T_DIM + n0 + col;
#pragma unroll
                for (int j = 0; j < 4; j++) {
                    float s = vv[j] * invs;
                    s = fminf(fmaxf(s, -50.f), 50.f);
                    po[j] = mask[mb + j] ? s : -50.f;
                }
                *(float4*)(Cf + ((size_t)blockIdx.z * S_DIM + m0 + row) * T_DIM + n0 + col) = o;
            } else {  // MODE 4: fp32 + bias
                float4 b4 = *(const float4*)(bias + n0 + col);
                float4 o = make_float4(v.x + b4.x, v.y + b4.y, v.z + b4.z, v.w + b4.w);
                *(float4*)(Cf + (size_t)(m0 + row) * ldc + n0 + col) = o;
            }
        }
    }
}

// ---------------------------------------------------------------------------
// Softmax: one warp per row of 256 scores; fp32 in, bf16 hi/lo out
// ---------------------------------------------------------------------------
__global__ void softmax_kernel(const float* __restrict__ S,
                               __nv_bfloat16* __restrict__ Ph,
                               __nv_bfloat16* __restrict__ Pl)
{
    int gw = (blockIdx.x * blockDim.x + threadIdx.x) >> 5;
    int lane = threadIdx.x & 31;
    const float* p = S + (size_t)gw * T_DIM;

    float4 v0 = *(const float4*)(p + lane * 4);
    float4 v1 = *(const float4*)(p + 128 + lane * 4);
    float v[8] = {v0.x, v0.y, v0.z, v0.w, v1.x, v1.y, v1.z, v1.w};

    float mx = v[0];
#pragma unroll
    for (int i = 1; i < 8; i++) mx = fmaxf(mx, v[i]);
#pragma unroll
    for (int o = 16; o; o >>= 1) mx = fmaxf(mx, __shfl_xor_sync(0xffffffffu, mx, o));

    float s = 0.f;
#pragma unroll
    for (int i = 0; i < 8; i++) { v[i] = __expf(v[i] - mx); s += v[i]; }
#pragma unroll
    for (int o = 16; o; o >>= 1) s += __shfl_xor_sync(0xffffffffu, s, o);

    float inv = 1.f / s;
#pragma unroll
    for (int i = 0; i < 8; i++) v[i] *= inv;

    uint32_t ph[4], pl[4];
    split_pair(v[0], v[1], ph[0], pl[0]);
    split_pair(v[2], v[3], ph[1], pl[1]);
    split_pair(v[4], v[5], ph[2], pl[2]);
    split_pair(v[6], v[7], ph[3], pl[3]);
    *(uint2*)(Ph + (size_t)gw * T_DIM + lane * 4)       = make_uint2(ph[0], ph[1]);
    *(uint2*)(Ph + (size_t)gw * T_DIM + 128 + lane * 4) = make_uint2(ph[2], ph[3]);
    *(uint2*)(Pl + (size_t)gw * T_DIM + lane * 4)       = make_uint2(pl[0], pl[1]);
    *(uint2*)(Pl + (size_t)gw * T_DIM + 128 + lane * 4) = make_uint2(pl[2], pl[3]);
}

// ---------------------------------------------------------------------------
// LayerNorm (residual_scale applied), one block per row
// ---------------------------------------------------------------------------
__device__ __forceinline__ float block_sum(float v)
{
    __shared__ float red[8];
#pragma unroll
    for (int o = 16; o; o >>= 1) v += __shfl_xor_sync(0xffffffffu, v, o);
    int w = threadIdx.x >> 5;
    if ((threadIdx.x & 31) == 0) red[w] = v;
    __syncthreads();
    float t = (threadIdx.x < 8) ? red[threadIdx.x] : 0.f;
    if (threadIdx.x < 32) {
#pragma unroll
        for (int o = 4; o; o >>= 1) t += __shfl_xor_sync(0xffffffffu, t, o);
        if (threadIdx.x == 0) red[0] = t;
    }
    __syncthreads();
    float r = red[0];
    __syncthreads();
    return r;
}

__global__ void ln_kernel(const float* __restrict__ D, const float* __restrict__ gamma,
                          const float* __restrict__ beta, const float* __restrict__ rsp,
                          float* __restrict__ out)
{
    int row = blockIdx.x;
    int tid = threadIdx.x;
    float rs = fminf(fmaxf(rsp[0], 0.f), 0.3f);

    const float* d = D + (size_t)row * H_DIM;
    float4 u0 = *(const float4*)(d + tid * 4);
    float4 u1 = *(const float4*)(d + 1024 + tid * 4);
    float x[8] = {rs*u0.x, rs*u0.y, rs*u0.z, rs*u0.w,
                  rs*u1.x, rs*u1.y, rs*u1.z, rs*u1.w};

    float ps = 0.f;
#pragma unroll
    for (int i = 0; i < 8; i++) ps += x[i];
    float mean = block_sum(ps) * (1.f / 2048.f);

    float pv = 0.f;
#pragma unroll
    for (int i = 0; i < 8; i++) { float dd = x[i] - mean; pv += dd * dd; }
    float var = block_sum(pv) * (1.f / 2048.f);
    float inv = rsqrtf(var + 1e-5f);

    float4 gz0 = *(const float4*)(gamma + tid * 4);
    float4 gz1 = *(const float4*)(gamma + 1024 + tid * 4);
    float4 bz0 = *(const float4*)(beta + tid * 4);
    float4 bz1 = *(const float4*)(beta + 1024 + tid * 4);

    float* o = out + (size_t)row * H_DIM;
    *(float4*)(o + tid * 4) = make_float4(
        (x[0]-mean)*inv*gz0.x + bz0.x, (x[1]-mean)*inv*gz0.y + bz0.y,
        (x[2]-mean)*inv*gz0.z + bz0.z, (x[3]-mean)*inv*gz0.w + bz0.w);
    *(float4*)(o + 1024 + tid * 4) = make_float4(
        (x[4]-mean)*inv*gz1.x + bz1.x, (x[5]-mean)*inv*gz1.y + bz1.y,
        (x[6]-mean)*inv*gz1.z + bz1.z, (x[7]-mean)*inv*gz1.w + bz1.w);
}

// ---------------------------------------------------------------------------
// Launch
// ---------------------------------------------------------------------------
#define SM256 (3 * (2 * (4096 + 256*32)))   // 73728
#define SM128 (3 * (2 * (4096 + 128*32)))   // 49152

extern "C" void kernel_launch(void* const* d_in, const int* in_sizes, int n_in,
                              void* d_out, int out_size)
{
    const float* hs    = (const float*)d_in[0];
    const float* at    = (const float*)d_in[1];
    const int*   mask  = (const int*)  d_in[2];
    const float* Wq    = (const float*)d_in[3];
    const float* bq    = (const float*)d_in[4];
    const float* Wk    = (const float*)d_in[5];
    const float* bk    = (const float*)d_in[6];
    const float* Wv    = (const float*)d_in[7];
    const float* bv    = (const float*)d_in[8];
    const float* Wo    = (const float*)d_in[9];
    const float* bo    = (const float*)d_in[10];
    const float* gamma = (const float*)d_in[11];
    const float* beta  = (const float*)d_in[12];
    const float* rsp   = (const float*)d_in[13];
    float* out = (float*)d_out;

    __nv_bfloat16 *hsh, *hsl, *ath, *atl, *Wqh, *Wql, *Wkh, *Wkl, *Wvh, *Wvl, *Woh, *Wol;
    __nv_bfloat16 *Qh, *Ql, *Kh, *Kl, *Vth, *Vtl, *Ph, *Pl, *Ch, *Cl;
    float *Sb, *Db;
    cudaGetSymbolAddress((void**)&hsh, g_hsh); cudaGetSymbolAddress((void**)&hsl, g_hsl);
    cudaGetSymbolAddress((void**)&ath, g_ath); cudaGetSymbolAddress((void**)&atl, g_atl);
    cudaGetSymbolAddress((void**)&Wqh, g_Wqh); cudaGetSymbolAddress((void**)&Wql, g_Wql);
    cudaGetSymbolAddress((void**)&Wkh, g_Wkh); cudaGetSymbolAddress((void**)&Wkl, g_Wkl);
    cudaGetSymbolAddress((void**)&Wvh, g_Wvh); cudaGetSymbolAddress((void**)&Wvl, g_Wvl);
    cudaGetSymbolAddress((void**)&Woh, g_Woh); cudaGetSymbolAddress((void**)&Wol, g_Wol);
    cudaGetSymbolAddress((void**)&Qh,  g_Qh);  cudaGetSymbolAddress((void**)&Ql,  g_Ql);
    cudaGetSymbolAddress((void**)&Kh,  g_Kh);  cudaGetSymbolAddress((void**)&Kl,  g_Kl);
    cudaGetSymbolAddress((void**)&Vth, g_Vth); cudaGetSymbolAddress((void**)&Vtl, g_Vtl);
    cudaGetSymbolAddress((void**)&Ph,  g_Ph);  cudaGetSymbolAddress((void**)&Pl,  g_Pl);
    cudaGetSymbolAddress((void**)&Ch,  g_Ch);  cudaGetSymbolAddress((void**)&Cl,  g_Cl);
    cudaGetSymbolAddress((void**)&Sb,  g_S);   cudaGetSymbolAddress((void**)&Db,  g_D);

    // Opt-in dynamic smem (immediate host-side calls; not graph nodes)
    cudaFuncSetAttribute(mma_gemm<0,256>, cudaFuncAttributeMaxDynamicSharedMemorySize, SM256);
    cudaFuncSetAttribute(mma_gemm<1,256>, cudaFuncAttributeMaxDynamicSharedMemorySize, SM256);
    cudaFuncSetAttribute(mma_gemm<2,256>, cudaFuncAttributeMaxDynamicSharedMemorySize, SM256);
    cudaFuncSetAttribute(mma_gemm<3,128>, cudaFuncAttributeMaxDynamicSharedMemorySize, SM128);
    cudaFuncSetAttribute(mma_gemm<4,256>, cudaFuncAttributeMaxDynamicSharedMemorySize, SM256);

    // Pre-pass: split all fp32 operands into bf16 hi/lo
    split_kernel<<<16384, 256>>>(hs, hsh, hsl);
    split_kernel<<<2048,  256>>>(at, ath, atl);
    split_kernel<<<4096,  256>>>(Wq, Wqh, Wql);
    split_kernel<<<4096,  256>>>(Wk, Wkh, Wkl);
    split_kernel<<<4096,  256>>>(Wv, Wvh, Wvl);
    split_kernel<<<4096,  256>>>(Wo, Woh, Wol);

    // Q projection -> Qh/Ql
    mma_gemm<0,256><<<dim3(8, 64), 256, SM256>>>(hsh, hsl, Wqh, Wql, bq, nullptr,
                                                 nullptr, Qh, Ql, 2048, 2048, 2048, 2048);
    // K projection -> Kh/Kl
    mma_gemm<0,256><<<dim3(8, 8), 256, SM256>>>(ath, atl, Wkh, Wkl, bk, nullptr,
                                                nullptr, Kh, Kl, 2048, 2048, 2048, 2048);
    // V projection (A=Wv, B=at) -> Vt hi/lo [b,h,d,t]
    mma_gemm<1,256><<<dim3(4, 16), 256, SM256>>>(Wvh, Wvl, ath, atl, bv, nullptr,
                                                 nullptr, Vth, Vtl, 2048, 2048, 2048, 0);
    // Scores per (b,h) -> fp32 S
    mma_gemm<2,256><<<dim3(1, 16, 64), 256, SM256>>>(Qh, Ql, Kh, Kl, nullptr, mask,
                                                     Sb, nullptr, nullptr, 128, 2048, 2048, 256);
    // Softmax: 131072 rows
    softmax_kernel<<<16384, 256>>>(Sb, Ph, Pl);
    // PV per (b,h) -> ctx hi/lo
    mma_gemm<3,128><<<dim3(1, 16, 64), 256, SM128>>>(Ph, Pl, Vth, Vtl, nullptr, nullptr,
                                                     nullptr, Ch, Cl, 256, 256, 256, 0);
    // O projection -> fp32 D
    mma_gemm<4,256><<<dim3(8, 64), 256, SM256>>>(Ch, Cl, Woh, Wol, bo, nullptr,
                                                 Db, nullptr, nullptr, 2048, 2048, 2048, 2048);
    // residual scale + LayerNorm
    ln_kernel<<<8192, 256>>>(Db, gamma, beta, rsp, out);
}

// round 7
// speedup vs baseline: 1.3498x; 1.3498x over previous
#include <cuda_runtime.h>
#include <cuda_bf16.h>
#include <cstdint>
#include <math.h>

#define B_DIM 4
#define S_DIM 2048
#define T_DIM 256
#define H_DIM 2048
#define NHEAD 16
#define HD_DIM 128

// GEMM tiling: 128x128 CTA tile, BK=16, 3-stage cp.async ring, 2 CTAs/SM
#define BK 16
#define TILE_B 4096          // 128 rows x 32B (16 bf16)
#define STAGE_B 16384        // Ahi,Alo,Bhi,Blo
#define NSTAGE 3
#define SMEM_BYTES 49152
#define STAGE_PITCH 68       // fp32 epilogue staging pitch

// ---------------------------------------------------------------------------
// Persistent scratch (device globals)
// ---------------------------------------------------------------------------
__device__ __nv_bfloat16 g_hsh[8192*2048], g_hsl[8192*2048];
__device__ __nv_bfloat16 g_ath[1024*2048], g_atl[1024*2048];
__device__ __nv_bfloat16 g_Wqh[2048*2048], g_Wql[2048*2048];
__device__ __nv_bfloat16 g_Wkh[2048*2048], g_Wkl[2048*2048];
__device__ __nv_bfloat16 g_Wvh[2048*2048], g_Wvl[2048*2048];
__device__ __nv_bfloat16 g_Woh[2048*2048], g_Wol[2048*2048];
__device__ __nv_bfloat16 g_Qh[8192*2048],  g_Ql[8192*2048];
__device__ __nv_bfloat16 g_Kh[1024*2048],  g_Kl[1024*2048];
__device__ __nv_bfloat16 g_Vth[64*128*256], g_Vtl[64*128*256];
__device__ float         g_S[64u*2048u*256u];
__device__ __nv_bfloat16 g_Ph[64u*2048u*256u], g_Pl[64u*2048u*256u];
__device__ __nv_bfloat16 g_Ch[8192*2048],  g_Cl[8192*2048];
__device__ float         g_D[8192*2048];

// ---------------------------------------------------------------------------
// Helpers
// ---------------------------------------------------------------------------
__device__ __forceinline__ uint32_t smem_to_u32(const void* p) {
    uint32_t a;
    asm("{ .reg .u64 t; cvta.to.shared.u64 t, %1; cvt.u32.u64 %0, t; }" : "=r"(a) : "l"(p));
    return a;
}
__device__ __forceinline__ void cp16(uint32_t dst, const void* src) {
    asm volatile("cp.async.cg.shared.global [%0], [%1], 16;" :: "r"(dst), "l"(src));
}
#define CP_COMMIT() asm volatile("cp.async.commit_group;")
#define CP_WAIT1()  asm volatile("cp.async.wait_group 1;")

__device__ __forceinline__ void ldmx4(uint32_t* r, uint32_t addr) {
    asm volatile("ldmatrix.sync.aligned.m8n8.x4.shared.b16 {%0,%1,%2,%3}, [%4];"
                 : "=r"(r[0]), "=r"(r[1]), "=r"(r[2]), "=r"(r[3]) : "r"(addr));
}
__device__ __forceinline__ void mma16816(float* c, const uint32_t* a, const uint32_t* b) {
    asm volatile("mma.sync.aligned.m16n8k16.row.col.f32.bf16.bf16.f32 "
                 "{%0,%1,%2,%3}, {%4,%5,%6,%7}, {%8,%9}, {%0,%1,%2,%3};"
                 : "+f"(c[0]), "+f"(c[1]), "+f"(c[2]), "+f"(c[3])
                 : "r"(a[0]), "r"(a[1]), "r"(a[2]), "r"(a[3]), "r"(b[0]), "r"(b[1]));
}
__device__ __forceinline__ void split_pair(float x0, float x1, uint32_t& hi, uint32_t& lo) {
    __nv_bfloat162 h = __floats2bfloat162_rn(x0, x1);
    float r0 = x0 - __bfloat162float(h.x);
    float r1 = x1 - __bfloat162float(h.y);
    __nv_bfloat162 l = __floats2bfloat162_rn(r0, r1);
    hi = *(uint32_t*)&h;
    lo = *(uint32_t*)&l;
}
// XOR-swizzled address within a 128x16(bf16) tile, pitch 32B
__device__ __forceinline__ uint32_t swaddr(uint32_t tile, int row, int seg) {
    return tile + row * 32 + ((seg << 4) ^ ((row & 4) << 2));
}

// ---------------------------------------------------------------------------
// Pre-pass: split fp32 -> bf16 hi/lo
// ---------------------------------------------------------------------------
__global__ void split_kernel(const float* __restrict__ in,
                             __nv_bfloat16* __restrict__ hi,
                             __nv_bfloat16* __restrict__ lo)
{
    int idx = blockIdx.x * blockDim.x + threadIdx.x;
    float4 v = ((const float4*)in)[idx];
    uint32_t h0, l0, h1, l1;
    split_pair(v.x, v.y, h0, l0);
    split_pair(v.z, v.w, h1, l1);
    ((uint2*)hi)[idx] = make_uint2(h0, h1);
    ((uint2*)lo)[idx] = make_uint2(l0, l1);
}

// ---------------------------------------------------------------------------
// Tensor-core GEMM: C = A[M,K] * B[N,K]^T, operands pre-split bf16 hi/lo
// 128x128 CTA tile, 8 warps (2x4), warp tile 64x32, 2 CTAs/SM
//   MODE 0: proj+bias -> hi/lo out     MODE 1: V-proj -> Vt hi/lo scatter
//   MODE 2: scores -> fp32 (scale/clip/mask)
//   MODE 3: PV -> ctx hi/lo scatter    MODE 4: proj+bias -> fp32
// ---------------------------------------------------------------------------
template<int MODE>
__global__ void __launch_bounds__(256, 2)
mma_gemm(const __nv_bfloat16* __restrict__ Ah, const __nv_bfloat16* __restrict__ Al,
         const __nv_bfloat16* __restrict__ Bh, const __nv_bfloat16* __restrict__ Bl,
         const float* __restrict__ bias, const int* __restrict__ mask,
         float* __restrict__ Cf, __nv_bfloat16* __restrict__ Ch,
         __nv_bfloat16* __restrict__ Cl, int K, int lda, int ldb, int ldc)
{
    __shared__ __align__(16) char smem[SMEM_BYTES];
    const int tid = threadIdx.x;
    const int wid = tid >> 5;
    const int lane = tid & 31;
    const int g = lane >> 2, ti = lane & 3;
    const int mwb = (wid >> 2) * 64;
    const int nwb = (wid & 3) * 32;
    const uint32_t sbase = smem_to_u32(smem);

    const int m0 = blockIdx.y * 128;
    const int n0 = blockIdx.x * 128;
    int bb = 0, hh = 0;
    size_t aoff = 0, boff = 0;
    if (MODE == 2) {
        bb = blockIdx.z >> 4; hh = blockIdx.z & 15;
        aoff = (size_t)bb * S_DIM * H_DIM + hh * HD_DIM;
        boff = (size_t)bb * T_DIM * H_DIM + hh * HD_DIM;
    }
    if (MODE == 3) {
        bb = blockIdx.z >> 4; hh = blockIdx.z & 15;
        aoff = (size_t)blockIdx.z * S_DIM * T_DIM;
        boff = (size_t)blockIdx.z * HD_DIM * T_DIM;
    }
    const __nv_bfloat16* pAh = Ah + aoff;
    const __nv_bfloat16* pAl = Al + aoff;
    const __nv_bfloat16* pBh = Bh + boff;
    const __nv_bfloat16* pBl = Bl + boff;

    // cp.async thread mapping: row = tid>>1 (0..127), seg = tid&1
    const int crow = tid >> 1;
    const int cseg = tid & 1;
    const size_t asrc = (size_t)(m0 + crow) * lda + cseg * 8;
    const size_t bsrc = (size_t)(n0 + crow) * ldb + cseg * 8;
    const uint32_t cdst = swaddr(sbase, crow, cseg);

    const int nchunk = K / BK;

    auto issue = [&](int c) {
        const uint32_t st = (c % NSTAGE) * STAGE_B;
        const int kt = c * BK;
        cp16(cdst + st,              pAh + asrc + kt);
        cp16(cdst + st + TILE_B,     pAl + asrc + kt);
        cp16(cdst + st + 2*TILE_B,   pBh + bsrc + kt);
        cp16(cdst + st + 3*TILE_B,   pBl + bsrc + kt);
    };

    float acc[4][4][4];
#pragma unroll
    for (int i = 0; i < 4; i++)
#pragma unroll
        for (int j = 0; j < 4; j++)
#pragma unroll
            for (int q = 0; q < 4; q++) acc[i][j][q] = 0.f;

    issue(0); CP_COMMIT();
    if (nchunk > 1) issue(1);
    CP_COMMIT();

    const int arow = lane & 15;
    const int aseg = lane >> 4;
    const int brow = (lane & 7) + ((lane >> 4) << 3);
    const int bseg = (lane >> 3) & 1;

    for (int c = 0; c < nchunk; c++) {
        CP_WAIT1();
        __syncthreads();
        if (c + 2 < nchunk) issue(c + 2);
        CP_COMMIT();

        const uint32_t sbuf = sbase + (c % NSTAGE) * STAGE_B;
        uint32_t ah[4][4], al[4][4];
#pragma unroll
        for (int mf = 0; mf < 4; mf++) {
            uint32_t ad = swaddr(sbuf, mwb + mf * 16 + arow, aseg);
            ldmx4(ah[mf], ad);
            ldmx4(al[mf], ad + TILE_B);
        }
#pragma unroll
        for (int np = 0; np < 2; np++) {
            uint32_t rh[4], rl[4];
            uint32_t bd = swaddr(sbuf + 2*TILE_B, nwb + np * 16 + brow, bseg);
            ldmx4(rh, bd);
            ldmx4(rl, bd + TILE_B);
#pragma unroll
            for (int mf = 0; mf < 4; mf++) {
                mma16816(acc[mf][2*np],   ah[mf], rh);
                mma16816(acc[mf][2*np+1], ah[mf], rh + 2);
                mma16816(acc[mf][2*np],   ah[mf], rl);
                mma16816(acc[mf][2*np+1], ah[mf], rl + 2);
                mma16816(acc[mf][2*np],   al[mf], rh);
                mma16816(acc[mf][2*np+1], al[mf], rh + 2);
            }
        }
        __syncthreads();
    }

    // Epilogue: two passes through fp32 SMEM stage -> coalesced stores
    float* stage = (float*)smem;
#pragma unroll
    for (int p = 0; p < 2; p++) {
        if (p) __syncthreads();
#pragma unroll
        for (int mf = 0; mf < 4; mf++)
#pragma unroll
            for (int e = 0; e < 2; e++) {
                const int nf = 2 * p + e;
                const int row = mwb + mf * 16 + g;
                const int cm = (wid & 3) * 16 + e * 8 + ti * 2;
                *(float2*)&stage[row * STAGE_PITCH + cm] =
                    make_float2(acc[mf][nf][0], acc[mf][nf][1]);
                *(float2*)&stage[(row + 8) * STAGE_PITCH + cm] =
                    make_float2(acc[mf][nf][2], acc[mf][nf][3]);
            }
        __syncthreads();
#pragma unroll
        for (int it = 0; it < 8; it++) {
            const int lin = it * 1024 + tid * 4;
            const int row = lin >> 6;
            const int cm = lin & 63;
            const int col = ((cm >> 4) << 5) + (p << 4) + (cm & 15);
            float4 v = *(float4*)&stage[row * STAGE_PITCH + cm];
            if (MODE == 0 || MODE == 1 || MODE == 3) {
                float b0 = 0.f, b1 = 0.f, b2 = 0.f, b3 = 0.f;
                size_t off;
                if (MODE == 0) {
                    float4 b4 = *(const float4*)(bias + n0 + col);
                    b0 = b4.x; b1 = b4.y; b2 = b4.z; b3 = b4.w;
                    off = (size_t)(m0 + row) * ldc + n0 + col;
                } else if (MODE == 1) {
                    const int gr = m0 + row;             // feature = h*128+d
                    const int h = gr >> 7, d = gr & 127;
                    const int n = n0 + col;              // b*256+t
                    const int b = n >> 8, t = n & 255;
                    b0 = b1 = b2 = b3 = bias[gr];
                    off = ((size_t)(b * NHEAD + h) * HD_DIM + d) * T_DIM + t;
                } else {
                    off = (size_t)(bb * S_DIM + m0 + row) * H_DIM + hh * HD_DIM + col;
                }
                uint32_t h0, l0, h1, l1;
                split_pair(v.x + b0, v.y + b1, h0, l0);
                split_pair(v.z + b2, v.w + b3, h1, l1);
                *(uint2*)(Ch + off) = make_uint2(h0, h1);
                *(uint2*)(Cl + off) = make_uint2(l0, l1);
            } else if (MODE == 2) {
                const float invs = 0.08838834764831845f;  // 1/sqrt(128)
                float vv[4] = {v.x, v.y, v.z, v.w};
                float4 o; float* po = &o.x;
                const int mb = bb * T_DIM + n0 + col;
#pragma unroll
                for (int j = 0; j < 4; j++) {
                    float s = vv[j] * invs;
                    s = fminf(fmaxf(s, -50.f), 50.f);
                    po[j] = mask[mb + j] ? s : -50.f;
                }
                *(float4*)(Cf + ((size_t)blockIdx.z * S_DIM + m0 + row) * T_DIM + n0 + col) = o;
            } else {  // MODE 4: fp32 + bias
                float4 b4 = *(const float4*)(bias + n0 + col);
                float4 o = make_float4(v.x + b4.x, v.y + b4.y, v.z + b4.z, v.w + b4.w);
                *(float4*)(Cf + (size_t)(m0 + row) * ldc + n0 + col) = o;
            }
        }
    }
}

// ---------------------------------------------------------------------------
// Softmax: one warp per row of 256 scores; fp32 in, bf16 hi/lo out
// ---------------------------------------------------------------------------
__global__ void softmax_kernel(const float* __restrict__ S,
                               __nv_bfloat16* __restrict__ Ph,
                               __nv_bfloat16* __restrict__ Pl)
{
    int gw = (blockIdx.x * blockDim.x + threadIdx.x) >> 5;
    int lane = threadIdx.x & 31;
    const float* p = S + (size_t)gw * T_DIM;

    float4 v0 = *(const float4*)(p + lane * 4);
    float4 v1 = *(const float4*)(p + 128 + lane * 4);
    float v[8] = {v0.x, v0.y, v0.z, v0.w, v1.x, v1.y, v1.z, v1.w};

    float mx = v[0];
#pragma unroll
    for (int i = 1; i < 8; i++) mx = fmaxf(mx, v[i]);
#pragma unroll
    for (int o = 16; o; o >>= 1) mx = fmaxf(mx, __shfl_xor_sync(0xffffffffu, mx, o));

    float s = 0.f;
#pragma unroll
    for (int i = 0; i < 8; i++) { v[i] = __expf(v[i] - mx); s += v[i]; }
#pragma unroll
    for (int o = 16; o; o >>= 1) s += __shfl_xor_sync(0xffffffffu, s, o);

    float inv = 1.f / s;
#pragma unroll
    for (int i = 0; i < 8; i++) v[i] *= inv;

    uint32_t ph[4], pl[4];
    split_pair(v[0], v[1], ph[0], pl[0]);
    split_pair(v[2], v[3], ph[1], pl[1]);
    split_pair(v[4], v[5], ph[2], pl[2]);
    split_pair(v[6], v[7], ph[3], pl[3]);
    *(uint2*)(Ph + (size_t)gw * T_DIM + lane * 4)       = make_uint2(ph[0], ph[1]);
    *(uint2*)(Ph + (size_t)gw * T_DIM + 128 + lane * 4) = make_uint2(ph[2], ph[3]);
    *(uint2*)(Pl + (size_t)gw * T_DIM + lane * 4)       = make_uint2(pl[0], pl[1]);
    *(uint2*)(Pl + (size_t)gw * T_DIM + 128 + lane * 4) = make_uint2(pl[2], pl[3]);
}

// ---------------------------------------------------------------------------
// LayerNorm (residual_scale applied), one block per row
// ---------------------------------------------------------------------------
__device__ __forceinline__ float block_sum(float v)
{
    __shared__ float red[8];
#pragma unroll
    for (int o = 16; o; o >>= 1) v += __shfl_xor_sync(0xffffffffu, v, o);
    int w = threadIdx.x >> 5;
    if ((threadIdx.x & 31) == 0) red[w] = v;
    __syncthreads();
    float t = (threadIdx.x < 8) ? red[threadIdx.x] : 0.f;
    if (threadIdx.x < 32) {
#pragma unroll
        for (int o = 4; o; o >>= 1) t += __shfl_xor_sync(0xffffffffu, t, o);
        if (threadIdx.x == 0) red[0] = t;
    }
    __syncthreads();
    float r = red[0];
    __syncthreads();
    return r;
}

__global__ void ln_kernel(const float* __restrict__ D, const float* __restrict__ gamma,
                          const float* __restrict__ beta, const float* __restrict__ rsp,
                          float* __restrict__ out)
{
    int row = blockIdx.x;
    int tid = threadIdx.x;
    float rs = fminf(fmaxf(rsp[0], 0.f), 0.3f);

    const float* d = D + (size_t)row * H_DIM;
    float4 u0 = *(const float4*)(d + tid * 4);
    float4 u1 = *(const float4*)(d + 1024 + tid * 4);
    float x[8] = {rs*u0.x, rs*u0.y, rs*u0.z, rs*u0.w,
                  rs*u1.x, rs*u1.y, rs*u1.z, rs*u1.w};

    float ps = 0.f;
#pragma unroll
    for (int i = 0; i < 8; i++) ps += x[i];
    float mean = block_sum(ps) * (1.f / 2048.f);

    float pv = 0.f;
#pragma unroll
    for (int i = 0; i < 8; i++) { float dd = x[i] - mean; pv += dd * dd; }
    float var = block_sum(pv) * (1.f / 2048.f);
    float inv = rsqrtf(var + 1e-5f);

    float4 gz0 = *(const float4*)(gamma + tid * 4);
    float4 gz1 = *(const float4*)(gamma + 1024 + tid * 4);
    float4 bz0 = *(const float4*)(beta + tid * 4);
    float4 bz1 = *(const float4*)(beta + 1024 + tid * 4);

    float* o = out + (size_t)row * H_DIM;
    *(float4*)(o + tid * 4) = make_float4(
        (x[0]-mean)*inv*gz0.x + bz0.x, (x[1]-mean)*inv*gz0.y + bz0.y,
        (x[2]-mean)*inv*gz0.z + bz0.z, (x[3]-mean)*inv*gz0.w + bz0.w);
    *(float4*)(o + 1024 + tid * 4) = make_float4(
        (x[4]-mean)*inv*gz1.x + bz1.x, (x[5]-mean)*inv*gz1.y + bz1.y,
        (x[6]-mean)*inv*gz1.z + bz1.z, (x[7]-mean)*inv*gz1.w + bz1.w);
}

// ---------------------------------------------------------------------------
// Launch
// ---------------------------------------------------------------------------
extern "C" void kernel_launch(void* const* d_in, const int* in_sizes, int n_in,
                              void* d_out, int out_size)
{
    const float* hs    = (const float*)d_in[0];
    const float* at    = (const float*)d_in[1];
    const int*   mask  = (const int*)  d_in[2];
    const float* Wq    = (const float*)d_in[3];
    const float* bq    = (const float*)d_in[4];
    const float* Wk    = (const float*)d_in[5];
    const float* bk    = (const float*)d_in[6];
    const float* Wv    = (const float*)d_in[7];
    const float* bv    = (const float*)d_in[8];
    const float* Wo    = (const float*)d_in[9];
    const float* bo    = (const float*)d_in[10];
    const float* gamma = (const float*)d_in[11];
    const float* beta  = (const float*)d_in[12];
    const float* rsp   = (const float*)d_in[13];
    float* out = (float*)d_out;

    __nv_bfloat16 *hsh, *hsl, *ath, *atl, *Wqh, *Wql, *Wkh, *Wkl, *Wvh, *Wvl, *Woh, *Wol;
    __nv_bfloat16 *Qh, *Ql, *Kh, *Kl, *Vth, *Vtl, *Ph, *Pl, *Ch, *Cl;
    float *Sb, *Db;
    cudaGetSymbolAddress((void**)&hsh, g_hsh); cudaGetSymbolAddress((void**)&hsl, g_hsl);
    cudaGetSymbolAddress((void**)&ath, g_ath); cudaGetSymbolAddress((void**)&atl, g_atl);
    cudaGetSymbolAddress((void**)&Wqh, g_Wqh); cudaGetSymbolAddress((void**)&Wql, g_Wql);
    cudaGetSymbolAddress((void**)&Wkh, g_Wkh); cudaGetSymbolAddress((void**)&Wkl, g_Wkl);
    cudaGetSymbolAddress((void**)&Wvh, g_Wvh); cudaGetSymbolAddress((void**)&Wvl, g_Wvl);
    cudaGetSymbolAddress((void**)&Woh, g_Woh); cudaGetSymbolAddress((void**)&Wol, g_Wol);
    cudaGetSymbolAddress((void**)&Qh,  g_Qh);  cudaGetSymbolAddress((void**)&Ql,  g_Ql);
    cudaGetSymbolAddress((void**)&Kh,  g_Kh);  cudaGetSymbolAddress((void**)&Kl,  g_Kl);
    cudaGetSymbolAddress((void**)&Vth, g_Vth); cudaGetSymbolAddress((void**)&Vtl, g_Vtl);
    cudaGetSymbolAddress((void**)&Ph,  g_Ph);  cudaGetSymbolAddress((void**)&Pl,  g_Pl);
    cudaGetSymbolAddress((void**)&Ch,  g_Ch);  cudaGetSymbolAddress((void**)&Cl,  g_Cl);
    cudaGetSymbolAddress((void**)&Sb,  g_S);   cudaGetSymbolAddress((void**)&Db,  g_D);

    // Pre-pass: split all fp32 operands into bf16 hi/lo
    split_kernel<<<16384, 256>>>(hs, hsh, hsl);
    split_kernel<<<2048,  256>>>(at, ath, atl);
    split_kernel<<<4096,  256>>>(Wq, Wqh, Wql);
    split_kernel<<<4096,  256>>>(Wk, Wkh, Wkl);
    split_kernel<<<4096,  256>>>(Wv, Wvh, Wvl);
    split_kernel<<<4096,  256>>>(Wo, Woh, Wol);

    // Q projection -> Qh/Ql
    mma_gemm<0><<<dim3(16, 64, 1), 256>>>(hsh, hsl, Wqh, Wql, bq, nullptr,
                                          nullptr, Qh, Ql, 2048, 2048, 2048, 2048);
    // K projection -> Kh/Kl
    mma_gemm<0><<<dim3(16, 8, 1), 256>>>(ath, atl, Wkh, Wkl, bk, nullptr,
                                         nullptr, Kh, Kl, 2048, 2048, 2048, 2048);
    // V projection (A=Wv, B=at) -> Vt hi/lo [b,h,d,t]
    mma_gemm<1><<<dim3(8, 16, 1), 256>>>(Wvh, Wvl, ath, atl, bv, nullptr,
                                         nullptr, Vth, Vtl, 2048, 2048, 2048, 0);
    // Scores per (b,h) -> fp32 S
    mma_gemm<2><<<dim3(2, 16, 64), 256>>>(Qh, Ql, Kh, Kl, nullptr, mask,
                                          Sb, nullptr, nullptr, 128, 2048, 2048, 256);
    // Softmax: 131072 rows
    softmax_kernel<<<16384, 256>>>(Sb, Ph, Pl);
    // PV per (b,h) -> ctx hi/lo
    mma_gemm<3><<<dim3(1, 16, 64), 256>>>(Ph, Pl, Vth, Vtl, nullptr, nullptr,
                                          nullptr, Ch, Cl, 256, 256, 256, 0);
    // O projection -> fp32 D
    mma_gemm<4><<<dim3(16, 64, 1), 256>>>(Ch, Cl, Woh, Wol, bo, nullptr,
                                          Db, nullptr, nullptr, 2048, 2048, 2048, 2048);
    // residual scale + LayerNorm
    ln_kernel<<<8192, 256>>>(Db, gamma, beta, rsp, out);
}

// round 8
// speedup vs baseline: 1.3569x; 1.0053x over previous
#include <cuda_runtime.h>
#include <cuda_bf16.h>
#include <cstdint>
#include <math.h>

#define B_DIM 4
#define S_DIM 2048
#define T_DIM 256
#define H_DIM 2048
#define NHEAD 16
#define HD_DIM 128

// GEMM tiling: 128x128 CTA tile, BK=16, 3-stage cp.async ring, 2 CTAs/SM
#define BK 16
#define TILE_B 4096          // 128 rows x 32B (16 bf16)
#define STAGE_B 16384        // Ahi,Alo,Bhi,Blo
#define NSTAGE 3
#define SMEM_BYTES 49152
#define STAGE_PITCH 68       // fp32 epilogue staging pitch

// Fused scores+softmax kernel (BN=256)
#define SS_ATB 4096          // A hi tile (128x16 bf16)
#define SS_BTB 8192          // B hi tile (256x16 bf16)
#define SS_STAGE 24576       // Ahi,Alo,Bhi,Blo
#define SS_SMEM 73728        // 3 stages

// ---------------------------------------------------------------------------
// Persistent scratch (device globals)
// ---------------------------------------------------------------------------
__device__ __nv_bfloat16 g_hsh[8192*2048], g_hsl[8192*2048];
__device__ __nv_bfloat16 g_ath[1024*2048], g_atl[1024*2048];
__device__ __nv_bfloat16 g_Wqh[2048*2048], g_Wql[2048*2048];
__device__ __nv_bfloat16 g_Wkh[2048*2048], g_Wkl[2048*2048];
__device__ __nv_bfloat16 g_Wvh[2048*2048], g_Wvl[2048*2048];
__device__ __nv_bfloat16 g_Woh[2048*2048], g_Wol[2048*2048];
__device__ __nv_bfloat16 g_Qh[8192*2048],  g_Ql[8192*2048];
__device__ __nv_bfloat16 g_Kh[1024*2048],  g_Kl[1024*2048];
__device__ __nv_bfloat16 g_Vth[64*128*256], g_Vtl[64*128*256];
__device__ __nv_bfloat16 g_Ph[64u*2048u*256u], g_Pl[64u*2048u*256u];
__device__ __nv_bfloat16 g_Ch[8192*2048],  g_Cl[8192*2048];
__device__ float         g_D[8192*2048];

// ---------------------------------------------------------------------------
// Helpers
// ---------------------------------------------------------------------------
__device__ __forceinline__ uint32_t smem_to_u32(const void* p) {
    uint32_t a;
    asm("{ .reg .u64 t; cvta.to.shared.u64 t, %1; cvt.u32.u64 %0, t; }" : "=r"(a) : "l"(p));
    return a;
}
__device__ __forceinline__ void cp16(uint32_t dst, const void* src) {
    asm volatile("cp.async.cg.shared.global [%0], [%1], 16;" :: "r"(dst), "l"(src));
}
#define CP_COMMIT() asm volatile("cp.async.commit_group;")
#define CP_WAIT1()  asm volatile("cp.async.wait_group 1;")

__device__ __forceinline__ void ldmx4(uint32_t* r, uint32_t addr) {
    asm volatile("ldmatrix.sync.aligned.m8n8.x4.shared.b16 {%0,%1,%2,%3}, [%4];"
                 : "=r"(r[0]), "=r"(r[1]), "=r"(r[2]), "=r"(r[3]) : "r"(addr));
}
__device__ __forceinline__ void mma16816(float* c, const uint32_t* a, const uint32_t* b) {
    asm volatile("mma.sync.aligned.m16n8k16.row.col.f32.bf16.bf16.f32 "
                 "{%0,%1,%2,%3}, {%4,%5,%6,%7}, {%8,%9}, {%0,%1,%2,%3};"
                 : "+f"(c[0]), "+f"(c[1]), "+f"(c[2]), "+f"(c[3])
                 : "r"(a[0]), "r"(a[1]), "r"(a[2]), "r"(a[3]), "r"(b[0]), "r"(b[1]));
}
__device__ __forceinline__ void split_pair(float x0, float x1, uint32_t& hi, uint32_t& lo) {
    __nv_bfloat162 h = __floats2bfloat162_rn(x0, x1);
    float r0 = x0 - __bfloat162float(h.x);
    float r1 = x1 - __bfloat162float(h.y);
    __nv_bfloat162 l = __floats2bfloat162_rn(r0, r1);
    hi = *(uint32_t*)&h;
    lo = *(uint32_t*)&l;
}
// XOR-swizzled offset inside a (rows x 16 bf16) tile with 128-row subtiles
__device__ __forceinline__ uint32_t swz(int row, int seg) {
    return (row >> 7) * 4096 + (row & 127) * 32 + ((seg << 4) ^ ((row & 4) << 2));
}

// ---------------------------------------------------------------------------
// Pre-pass: split fp32 -> bf16 hi/lo
// ---------------------------------------------------------------------------
__global__ void split_kernel(const float* __restrict__ in,
                             __nv_bfloat16* __restrict__ hi,
                             __nv_bfloat16* __restrict__ lo)
{
    int idx = blockIdx.x * blockDim.x + threadIdx.x;
    float4 v = ((const float4*)in)[idx];
    uint32_t h0, l0, h1, l1;
    split_pair(v.x, v.y, h0, l0);
    split_pair(v.z, v.w, h1, l1);
    ((uint2*)hi)[idx] = make_uint2(h0, h1);
    ((uint2*)lo)[idx] = make_uint2(l0, l1);
}

// ---------------------------------------------------------------------------
// Tensor-core GEMM: C = A[M,K] * B[N,K]^T, operands pre-split bf16 hi/lo
// 128x128 CTA tile, 8 warps (2x4), warp tile 64x32, 2 CTAs/SM
//   MODE 0: proj+bias -> hi/lo out     MODE 1: V-proj -> Vt hi/lo scatter
//   MODE 3: PV -> ctx hi/lo scatter    MODE 4: proj+bias -> fp32
// ---------------------------------------------------------------------------
template<int MODE>
__global__ void __launch_bounds__(256, 2)
mma_gemm(const __nv_bfloat16* __restrict__ Ah, const __nv_bfloat16* __restrict__ Al,
         const __nv_bfloat16* __restrict__ Bh, const __nv_bfloat16* __restrict__ Bl,
         const float* __restrict__ bias,
         float* __restrict__ Cf, __nv_bfloat16* __restrict__ Ch,
         __nv_bfloat16* __restrict__ Cl, int K, int lda, int ldb, int ldc)
{
    __shared__ __align__(16) char smem[SMEM_BYTES];
    const int tid = threadIdx.x;
    const int wid = tid >> 5;
    const int lane = tid & 31;
    const int g = lane >> 2, ti = lane & 3;
    const int mwb = (wid >> 2) * 64;
    const int nwb = (wid & 3) * 32;
    const uint32_t sbase = smem_to_u32(smem);

    const int m0 = blockIdx.y * 128;
    const int n0 = blockIdx.x * 128;
    int bb = 0, hh = 0;
    size_t aoff = 0, boff = 0;
    if (MODE == 3) {
        bb = blockIdx.z >> 4; hh = blockIdx.z & 15;
        aoff = (size_t)blockIdx.z * S_DIM * T_DIM;
        boff = (size_t)blockIdx.z * HD_DIM * T_DIM;
    }
    const __nv_bfloat16* pAh = Ah + aoff;
    const __nv_bfloat16* pAl = Al + aoff;
    const __nv_bfloat16* pBh = Bh + boff;
    const __nv_bfloat16* pBl = Bl + boff;

    const int crow = tid >> 1;
    const int cseg = tid & 1;
    const size_t asrc = (size_t)(m0 + crow) * lda + cseg * 8;
    const size_t bsrc = (size_t)(n0 + crow) * ldb + cseg * 8;
    const uint32_t cdst = swz(crow, cseg);

    const int nchunk = K / BK;

    auto issue = [&](int c) {
        const uint32_t st = sbase + (c % NSTAGE) * STAGE_B;
        const int kt = c * BK;
        cp16(st + cdst,              pAh + asrc + kt);
        cp16(st + cdst + TILE_B,     pAl + asrc + kt);
        cp16(st + cdst + 2*TILE_B,   pBh + bsrc + kt);
        cp16(st + cdst + 3*TILE_B,   pBl + bsrc + kt);
    };

    float acc[4][4][4];
#pragma unroll
    for (int i = 0; i < 4; i++)
#pragma unroll
        for (int j = 0; j < 4; j++)
#pragma unroll
            for (int q = 0; q < 4; q++) acc[i][j][q] = 0.f;

    issue(0); CP_COMMIT();
    if (nchunk > 1) issue(1);
    CP_COMMIT();

    const int arow = lane & 15;
    const int aseg = lane >> 4;
    const int brow = (lane & 7) + ((lane >> 4) << 3);
    const int bseg = (lane >> 3) & 1;

    for (int c = 0; c < nchunk; c++) {
        CP_WAIT1();
        __syncthreads();           // data of stage c visible; all warps done reading stage (c+2)%3
        if (c + 2 < nchunk) issue(c + 2);
        CP_COMMIT();

        const uint32_t sbuf = sbase + (c % NSTAGE) * STAGE_B;
        uint32_t ah[4][4], al[4][4];
#pragma unroll
        for (int mf = 0; mf < 4; mf++) {
            uint32_t ad = sbuf + swz(mwb + mf * 16 + arow, aseg);
            ldmx4(ah[mf], ad);
            ldmx4(al[mf], ad + TILE_B);
        }
#pragma unroll
        for (int np = 0; np < 2; np++) {
            uint32_t rh[4], rl[4];
            uint32_t bd = sbuf + 2*TILE_B + swz(nwb + np * 16 + brow, bseg);
            ldmx4(rh, bd);
            ldmx4(rl, bd + TILE_B);
#pragma unroll
            for (int mf = 0; mf < 4; mf++) {
                mma16816(acc[mf][2*np],   ah[mf], rh);
                mma16816(acc[mf][2*np+1], ah[mf], rh + 2);
                mma16816(acc[mf][2*np],   ah[mf], rl);
                mma16816(acc[mf][2*np+1], ah[mf], rl + 2);
                mma16816(acc[mf][2*np],   al[mf], rh);
                mma16816(acc[mf][2*np+1], al[mf], rh + 2);
            }
        }
        // no bottom barrier: the next iteration's top barrier provides the ordering
    }
    __syncthreads();               // all warps done with smem stages before epilogue reuse

    // Epilogue: two passes through fp32 SMEM stage -> coalesced stores
    float* stage = (float*)smem;
#pragma unroll
    for (int p = 0; p < 2; p++) {
        if (p) __syncthreads();
#pragma unroll
        for (int mf = 0; mf < 4; mf++)
#pragma unroll
            for (int e = 0; e < 2; e++) {
                const int nf = 2 * p + e;
                const int row = mwb + mf * 16 + g;
                const int cm = (wid & 3) * 16 + e * 8 + ti * 2;
                *(float2*)&stage[row * STAGE_PITCH + cm] =
                    make_float2(acc[mf][nf][0], acc[mf][nf][1]);
                *(float2*)&stage[(row + 8) * STAGE_PITCH + cm] =
                    make_float2(acc[mf][nf][2], acc[mf][nf][3]);
            }
        __syncthreads();
#pragma unroll
        for (int it = 0; it < 8; it++) {
            const int lin = it * 1024 + tid * 4;
            const int row = lin >> 6;
            const int cm = lin & 63;
            const int col = ((cm >> 4) << 5) + (p << 4) + (cm & 15);
            float4 v = *(float4*)&stage[row * STAGE_PITCH + cm];
            if (MODE == 0 || MODE == 1 || MODE == 3) {
                float b0 = 0.f, b1 = 0.f, b2 = 0.f, b3 = 0.f;
                size_t off;
                if (MODE == 0) {
                    float4 b4 = *(const float4*)(bias + n0 + col);
                    b0 = b4.x; b1 = b4.y; b2 = b4.z; b3 = b4.w;
                    off = (size_t)(m0 + row) * ldc + n0 + col;
                } else if (MODE == 1) {
                    const int gr = m0 + row;             // feature = h*128+d
                    const int h = gr >> 7, d = gr & 127;
                    const int n = n0 + col;              // b*256+t
                    const int b = n >> 8, t = n & 255;
                    b0 = b1 = b2 = b3 = bias[gr];
                    off = ((size_t)(b * NHEAD + h) * HD_DIM + d) * T_DIM + t;
                } else {
                    off = (size_t)(bb * S_DIM + m0 + row) * H_DIM + hh * HD_DIM + col;
                }
                uint32_t h0, l0, h1, l1;
                split_pair(v.x + b0, v.y + b1, h0, l0);
                split_pair(v.z + b2, v.w + b3, h1, l1);
                *(uint2*)(Ch + off) = make_uint2(h0, h1);
                *(uint2*)(Cl + off) = make_uint2(l0, l1);
            } else {  // MODE 4: fp32 + bias
                float4 b4 = *(const float4*)(bias + n0 + col);
                float4 o = make_float4(v.x + b4.x, v.y + b4.y, v.z + b4.z, v.w + b4.w);
                *(float4*)(Cf + (size_t)(m0 + row) * ldc + n0 + col) = o;
            }
        }
    }
}

// ---------------------------------------------------------------------------
// Fused scores + softmax: per (b,h), tile 128(q-rows) x 256(T) in one CTA.
// S = clip(QK^T/sqrt(d)) masked; softmax per row; write P hi/lo directly.
// Warp tile 64x64 (2x4 warps), acc[4][8][4].
// ---------------------------------------------------------------------------
__global__ void __launch_bounds__(256, 1)
scores_softmax_kernel(const __nv_bfloat16* __restrict__ Qh, const __nv_bfloat16* __restrict__ Ql,
                      const __nv_bfloat16* __restrict__ Kh, const __nv_bfloat16* __restrict__ Kl,
                      const int* __restrict__ mask,
                      __nv_bfloat16* __restrict__ Ph, __nv_bfloat16* __restrict__ Pl)
{
    extern __shared__ __align__(16) char dsm[];
    __shared__ float red[128][4];
    __shared__ int smask[T_DIM];

    const int tid = threadIdx.x;
    const int wid = tid >> 5;
    const int lane = tid & 31;
    const int g = lane >> 2, ti = lane & 3;
    const int mwb = (wid >> 2) * 64;
    const int nwb = (wid & 3) * 64;
    const uint32_t sbase = smem_to_u32(dsm);

    const int m0 = blockIdx.y * 128;
    const int z = blockIdx.z;
    const int bb = z >> 4, hh = z & 15;
    const __nv_bfloat16* pQh = Qh + (size_t)bb * S_DIM * H_DIM + hh * HD_DIM;
    const __nv_bfloat16* pQl = Ql + (size_t)bb * S_DIM * H_DIM + hh * HD_DIM;
    const __nv_bfloat16* pKh = Kh + (size_t)bb * T_DIM * H_DIM + hh * HD_DIM;
    const __nv_bfloat16* pKl = Kl + (size_t)bb * T_DIM * H_DIM + hh * HD_DIM;

    smask[tid] = mask[bb * T_DIM + tid];   // blockDim == T_DIM == 256

    const int crow = tid >> 1, cseg = tid & 1;
    const size_t qsrc  = (size_t)(m0 + crow) * H_DIM + cseg * 8;
    const size_t ksrc0 = (size_t)crow * H_DIM + cseg * 8;
    const size_t ksrc1 = (size_t)(crow + 128) * H_DIM + cseg * 8;
    const uint32_t adst = swz(crow, cseg);
    const uint32_t bdst0 = swz(crow, cseg);
    const uint32_t bdst1 = swz(crow + 128, cseg);

    auto issue = [&](int c) {
        const uint32_t st = sbase + (c % 3) * SS_STAGE;
        const int kt = c * BK;
        cp16(st + adst,                       pQh + qsrc + kt);
        cp16(st + adst + SS_ATB,              pQl + qsrc + kt);
        cp16(st + 2*SS_ATB + bdst0,           pKh + ksrc0 + kt);
        cp16(st + 2*SS_ATB + bdst1,           pKh + ksrc1 + kt);
        cp16(st + 2*SS_ATB + SS_BTB + bdst0,  pKl + ksrc0 + kt);
        cp16(st + 2*SS_ATB + SS_BTB + bdst1,  pKl + ksrc1 + kt);
    };

    float acc[4][8][4];
#pragma unroll
    for (int i = 0; i < 4; i++)
#pragma unroll
        for (int j = 0; j < 8; j++)
#pragma unroll
            for (int q = 0; q < 4; q++) acc[i][j][q] = 0.f;

    issue(0); CP_COMMIT();
    issue(1); CP_COMMIT();

    const int arow = lane & 15;
    const int aseg = lane >> 4;
    const int brow = (lane & 7) + ((lane >> 4) << 3);
    const int bseg = (lane >> 3) & 1;

    for (int c = 0; c < 8; c++) {          // K = HD = 128
        CP_WAIT1();
        __syncthreads();
        if (c + 2 < 8) issue(c + 2);
        CP_COMMIT();

        const uint32_t sbuf = sbase + (c % 3) * SS_STAGE;
        uint32_t ah[4][4], al[4][4];
#pragma unroll
        for (int mf = 0; mf < 4; mf++) {
            uint32_t ad = sbuf + swz(mwb + mf * 16 + arow, aseg);
            ldmx4(ah[mf], ad);
            ldmx4(al[mf], ad + SS_ATB);
        }
#pragma unroll
        for (int np = 0; np < 4; np++) {
            uint32_t rh[4], rl[4];
            uint32_t bd = sbuf + 2*SS_ATB + swz(nwb + np * 16 + brow, bseg);
            ldmx4(rh, bd);
            ldmx4(rl, bd + SS_BTB);
#pragma unroll
            for (int mf = 0; mf < 4; mf++) {
                mma16816(acc[mf][2*np],   ah[mf], rh);
                mma16816(acc[mf][2*np+1], ah[mf], rh + 2);
                mma16816(acc[mf][2*np],   ah[mf], rl);
                mma16816(acc[mf][2*np+1], ah[mf], rl + 2);
                mma16816(acc[mf][2*np],   al[mf], rh);
                mma16816(acc[mf][2*np+1], al[mf], rh + 2);
            }
        }
    }
    __syncthreads();

    // ---- mask/scale/clip + per-row softmax (rows span 4 n-warps) ----
    const float invs = 0.08838834764831845f;   // 1/sqrt(128)
    float rmax[4][2], rsum[4][2];
#pragma unroll
    for (int mf = 0; mf < 4; mf++) {
        float mx0 = -1e30f, mx1 = -1e30f;
#pragma unroll
        for (int nf = 0; nf < 8; nf++) {
            const int col = nwb + nf * 8 + ti * 2;
            const bool k0 = smask[col] != 0;
            const bool k1 = smask[col + 1] != 0;
            float* a = acc[mf][nf];
            a[0] = k0 ? fminf(fmaxf(a[0] * invs, -50.f), 50.f) : -50.f;
            a[1] = k1 ? fminf(fmaxf(a[1] * invs, -50.f), 50.f) : -50.f;
            a[2] = k0 ? fminf(fmaxf(a[2] * invs, -50.f), 50.f) : -50.f;
            a[3] = k1 ? fminf(fmaxf(a[3] * invs, -50.f), 50.f) : -50.f;
            mx0 = fmaxf(mx0, fmaxf(a[0], a[1]));
            mx1 = fmaxf(mx1, fmaxf(a[2], a[3]));
        }
        mx0 = fmaxf(mx0, __shfl_xor_sync(0xffffffffu, mx0, 1));
        mx0 = fmaxf(mx0, __shfl_xor_sync(0xffffffffu, mx0, 2));
        mx1 = fmaxf(mx1, __shfl_xor_sync(0xffffffffu, mx1, 1));
        mx1 = fmaxf(mx1, __shfl_xor_sync(0xffffffffu, mx1, 2));
        if (ti == 0) {
            red[mwb + mf * 16 + g][wid & 3]     = mx0;
            red[mwb + mf * 16 + g + 8][wid & 3] = mx1;
        }
    }
    __syncthreads();
#pragma unroll
    for (int mf = 0; mf < 4; mf++) {
        float4 r0 = *(float4*)red[mwb + mf * 16 + g];
        rmax[mf][0] = fmaxf(fmaxf(r0.x, r0.y), fmaxf(r0.z, r0.w));
        float4 r1 = *(float4*)red[mwb + mf * 16 + g + 8];
        rmax[mf][1] = fmaxf(fmaxf(r1.x, r1.y), fmaxf(r1.z, r1.w));
    }
    __syncthreads();
#pragma unroll
    for (int mf = 0; mf < 4; mf++) {
        float s0 = 0.f, s1 = 0.f;
#pragma unroll
        for (int nf = 0; nf < 8; nf++) {
            float* a = acc[mf][nf];
            a[0] = __expf(a[0] - rmax[mf][0]); s0 += a[0];
            a[1] = __expf(a[1] - rmax[mf][0]); s0 += a[1];
            a[2] = __expf(a[2] - rmax[mf][1]); s1 += a[2];
            a[3] = __expf(a[3] - rmax[mf][1]); s1 += a[3];
        }
        s0 += __shfl_xor_sync(0xffffffffu, s0, 1);
        s0 += __shfl_xor_sync(0xffffffffu, s0, 2);
        s1 += __shfl_xor_sync(0xffffffffu, s1, 1);
        s1 += __shfl_xor_sync(0xffffffffu, s1, 2);
        if (ti == 0) {
            red[mwb + mf * 16 + g][wid & 3]     = s0;
            red[mwb + mf * 16 + g + 8][wid & 3] = s1;
        }
    }
    __syncthreads();
#pragma unroll
    for (int mf = 0; mf < 4; mf++) {
        float4 r0 = *(float4*)red[mwb + mf * 16 + g];
        rsum[mf][0] = 1.f / (r0.x + r0.y + r0.z + r0.w);
        float4 r1 = *(float4*)red[mwb + mf * 16 + g + 8];
        rsum[mf][1] = 1.f / (r1.x + r1.y + r1.z + r1.w);
    }

    // ---- staged store of P hi/lo (4 passes of 128x64 fp32) ----
    float* stage = (float*)dsm;
    const int wp = nwb >> 6;     // pass this warp's columns belong to
#pragma unroll
    for (int p = 0; p < 4; p++) {
        if (p) __syncthreads();
        if (wp == p) {
#pragma unroll
            for (int mf = 0; mf < 4; mf++)
#pragma unroll
                for (int nf = 0; nf < 8; nf++) {
                    const int row = mwb + mf * 16 + g;
                    const int cm = nf * 8 + ti * 2;
                    *(float2*)&stage[row * STAGE_PITCH + cm] =
                        make_float2(acc[mf][nf][0] * rsum[mf][0],
                                    acc[mf][nf][1] * rsum[mf][0]);
                    *(float2*)&stage[(row + 8) * STAGE_PITCH + cm] =
                        make_float2(acc[mf][nf][2] * rsum[mf][1],
                                    acc[mf][nf][3] * rsum[mf][1]);
                }
        }
        __syncthreads();
#pragma unroll
        for (int it = 0; it < 8; it++) {
            const int lin = it * 1024 + tid * 4;
            const int row = lin >> 6;
            const int cm = lin & 63;
            const int col = p * 64 + cm;
            float4 v = *(float4*)&stage[row * STAGE_PITCH + cm];
            uint32_t h0, l0, h1, l1;
            split_pair(v.x, v.y, h0, l0);
            split_pair(v.z, v.w, h1, l1);
            size_t off = ((size_t)z * S_DIM + m0 + row) * T_DIM + col;
            *(uint2*)(Ph + off) = make_uint2(h0, h1);
            *(uint2*)(Pl + off) = make_uint2(l0, l1);
        }
    }
}

// ---------------------------------------------------------------------------
// LayerNorm (residual_scale applied), one block per row
// ---------------------------------------------------------------------------
__device__ __forceinline__ float block_sum(float v)
{
    __shared__ float red[8];
#pragma unroll
    for (int o = 16; o; o >>= 1) v += __shfl_xor_sync(0xffffffffu, v, o);
    int w = threadIdx.x >> 5;
    if ((threadIdx.x & 31) == 0) red[w] = v;
    __syncthreads();
    float t = (threadIdx.x < 8) ? red[threadIdx.x] : 0.f;
    if (threadIdx.x < 32) {
#pragma unroll
        for (int o = 4; o; o >>= 1) t += __shfl_xor_sync(0xffffffffu, t, o);
        if (threadIdx.x == 0) red[0] = t;
    }
    __syncthreads();
    float r = red[0];
    __syncthreads();
    return r;
}

__global__ void ln_kernel(const float* __restrict__ D, const float* __restrict__ gamma,
                          const float* __restrict__ beta, const float* __restrict__ rsp,
                          float* __restrict__ out)
{
    int row = blockIdx.x;
    int tid = threadIdx.x;
    float rs = fminf(fmaxf(rsp[0], 0.f), 0.3f);

    const float* d = D + (size_t)row * H_DIM;
    float4 u0 = *(const float4*)(d + tid * 4);
    float4 u1 = *(const float4*)(d + 1024 + tid * 4);
    float x[8] = {rs*u0.x, rs*u0.y, rs*u0.z, rs*u0.w,
                  rs*u1.x, rs*u1.y, rs*u1.z, rs*u1.w};

    float ps = 0.f;
#pragma unroll
    for (int i = 0; i < 8; i++) ps += x[i];
    float mean = block_sum(ps) * (1.f / 2048.f);

    float pv = 0.f;
#pragma unroll
    for (int i = 0; i < 8; i++) { float dd = x[i] - mean; pv += dd * dd; }
    float var = block_sum(pv) * (1.f / 2048.f);
    float inv = rsqrtf(var + 1e-5f);

    float4 gz0 = *(const float4*)(gamma + tid * 4);
    float4 gz1 = *(const float4*)(gamma + 1024 + tid * 4);
    float4 bz0 = *(const float4*)(beta + tid * 4);
    float4 bz1 = *(const float4*)(beta + 1024 + tid * 4);

    float* o = out + (size_t)row * H_DIM;
    *(float4*)(o + tid * 4) = make_float4(
        (x[0]-mean)*inv*gz0.x + bz0.x, (x[1]-mean)*inv*gz0.y + bz0.y,
        (x[2]-mean)*inv*gz0.z + bz0.z, (x[3]-mean)*inv*gz0.w + bz0.w);
    *(float4*)(o + 1024 + tid * 4) = make_float4(
        (x[4]-mean)*inv*gz1.x + bz1.x, (x[5]-mean)*inv*gz1.y + bz1.y,
        (x[6]-mean)*inv*gz1.z + bz1.z, (x[7]-mean)*inv*gz1.w + bz1.w);
}

// ---------------------------------------------------------------------------
// Launch
// ---------------------------------------------------------------------------
extern "C" void kernel_launch(void* const* d_in, const int* in_sizes, int n_in,
                              void* d_out, int out_size)
{
    const float* hs    = (const float*)d_in[0];
    const float* at    = (const float*)d_in[1];
    const int*   mask  = (const int*)  d_in[2];
    const float* Wq    = (const float*)d_in[3];
    const float* bq    = (const float*)d_in[4];
    const float* Wk    = (const float*)d_in[5];
    const float* bk    = (const float*)d_in[6];
    const float* Wv    = (const float*)d_in[7];
    const float* bv    = (const float*)d_in[8];
    const float* Wo    = (const float*)d_in[9];
    const float* bo    = (const float*)d_in[10];
    const float* gamma = (const float*)d_in[11];
    const float* beta  = (const float*)d_in[12];
    const float* rsp   = (const float*)d_in[13];
    float* out = (float*)d_out;

    __nv_bfloat16 *hsh, *hsl, *ath, *atl, *Wqh, *Wql, *Wkh, *Wkl, *Wvh, *Wvl, *Woh, *Wol;
    __nv_bfloat16 *Qh, *Ql, *Kh, *Kl, *Vth, *Vtl, *Ph, *Pl, *Ch, *Cl;
    float *Db;
    cudaGetSymbolAddress((void**)&hsh, g_hsh); cudaGetSymbolAddress((void**)&hsl, g_hsl);
    cudaGetSymbolAddress((void**)&ath, g_ath); cudaGetSymbolAddress((void**)&atl, g_atl);
    cudaGetSymbolAddress((void**)&Wqh, g_Wqh); cudaGetSymbolAddress((void**)&Wql, g_Wql);
    cudaGetSymbolAddress((void**)&Wkh, g_Wkh); cudaGetSymbolAddress((void**)&Wkl, g_Wkl);
    cudaGetSymbolAddress((void**)&Wvh, g_Wvh); cudaGetSymbolAddress((void**)&Wvl, g_Wvl);
    cudaGetSymbolAddress((void**)&Woh, g_Woh); cudaGetSymbolAddress((void**)&Wol, g_Wol);
    cudaGetSymbolAddress((void**)&Qh,  g_Qh);  cudaGetSymbolAddress((void**)&Ql,  g_Ql);
    cudaGetSymbolAddress((void**)&Kh,  g_Kh);  cudaGetSymbolAddress((void**)&Kl,  g_Kl);
    cudaGetSymbolAddress((void**)&Vth, g_Vth); cudaGetSymbolAddress((void**)&Vtl, g_Vtl);
    cudaGetSymbolAddress((void**)&Ph,  g_Ph);  cudaGetSymbolAddress((void**)&Pl,  g_Pl);
    cudaGetSymbolAddress((void**)&Ch,  g_Ch);  cudaGetSymbolAddress((void**)&Cl,  g_Cl);
    cudaGetSymbolAddress((void**)&Db,  g_D);

    cudaFuncSetAttribute(scores_softmax_kernel,
                         cudaFuncAttributeMaxDynamicSharedMemorySize, SS_SMEM);

    // Pre-pass: split all fp32 operands into bf16 hi/lo
    split_kernel<<<16384, 256>>>(hs, hsh, hsl);
    split_kernel<<<2048,  256>>>(at, ath, atl);
    split_kernel<<<4096,  256>>>(Wq, Wqh, Wql);
    split_kernel<<<4096,  256>>>(Wk, Wkh, Wkl);
    split_kernel<<<4096,  256>>>(Wv, Wvh, Wvl);
    split_kernel<<<4096,  256>>>(Wo, Woh, Wol);

    // Q projection -> Qh/Ql
    mma_gemm<0><<<dim3(16, 64, 1), 256>>>(hsh, hsl, Wqh, Wql, bq,
                                          nullptr, Qh, Ql, 2048, 2048, 2048, 2048);
    // K projection -> Kh/Kl
    mma_gemm<0><<<dim3(16, 8, 1), 256>>>(ath, atl, Wkh, Wkl, bk,
                                         nullptr, Kh, Kl, 2048, 2048, 2048, 2048);
    // V projection (A=Wv, B=at) -> Vt hi/lo [b,h,d,t]
    mma_gemm<1><<<dim3(8, 16, 1), 256>>>(Wvh, Wvl, ath, atl, bv,
                                         nullptr, Vth, Vtl, 2048, 2048, 2048, 0);
    // Fused scores + softmax -> P hi/lo
    scores_softmax_kernel<<<dim3(1, 16, 64), 256, SS_SMEM>>>(Qh, Ql, Kh, Kl, mask, Ph, Pl);
    // PV per (b,h) -> ctx hi/lo
    mma_gemm<3><<<dim3(1, 16, 64), 256>>>(Ph, Pl, Vth, Vtl, nullptr,
                                          nullptr, Ch, Cl, 256, 256, 256, 0);
    // O projection -> fp32 D
    mma_gemm<4><<<dim3(16, 64, 1), 256>>>(Ch, Cl, Woh, Wol, bo,
                                          Db, nullptr, nullptr, 2048, 2048, 2048, 2048);
    // residual scale + LayerNorm
    ln_kernel<<<8192, 256>>>(Db, gamma, beta, rsp, out);
}

// round 9
// speedup vs baseline: 1.3942x; 1.0275x over previous
#include <cuda_runtime.h>
#include <cuda_bf16.h>
#include <cstdint>
#include <math.h>

#define B_DIM 4
#define S_DIM 2048
#define T_DIM 256
#define H_DIM 2048
#define NHEAD 16
#define HD_DIM 128

// GEMM tiling: 128x128 CTA tile, BK=16, 3-stage cp.async ring, 2 CTAs/SM
#define BK 16
#define TILE_B 4096          // 128 rows x 32B (16 bf16)
#define STAGE_B 16384        // Ahi,Alo,Bhi,Blo
#define NSTAGE 3
#define SMEM_BYTES 49152
#define STAGE_PITCH 68       // fp32 epilogue staging pitch

// Fused attention kernel
#define SS_ATB 4096          // A hi tile (128x16 bf16)
#define SS_BTB 8192          // B hi tile (256x16 bf16)
#define SS_STAGE 24576       // Ahi,Alo,Bhi,Blo (scores mainloop)
#define VOFF 131072          // V ring offset (after 16x8KB P tiles)
#define SS_SMEM (VOFF + 3*8192)   // 155648

// ---------------------------------------------------------------------------
// Persistent scratch (device globals)
// ---------------------------------------------------------------------------
__device__ __nv_bfloat16 g_hsh[8192*2048], g_hsl[8192*2048];
__device__ __nv_bfloat16 g_ath[1024*2048], g_atl[1024*2048];
__device__ __nv_bfloat16 g_Wqh[2048*2048], g_Wql[2048*2048];
__device__ __nv_bfloat16 g_Wkh[2048*2048], g_Wkl[2048*2048];
__device__ __nv_bfloat16 g_Wvh[2048*2048], g_Wvl[2048*2048];
__device__ __nv_bfloat16 g_Woh[2048*2048], g_Wol[2048*2048];
__device__ __nv_bfloat16 g_Qh[8192*2048],  g_Ql[8192*2048];
__device__ __nv_bfloat16 g_Kh[1024*2048],  g_Kl[1024*2048];
__device__ __nv_bfloat16 g_Vth[64*128*256], g_Vtl[64*128*256];
__device__ __nv_bfloat16 g_Ch[8192*2048],  g_Cl[8192*2048];
__device__ float         g_D[8192*2048];

// ---------------------------------------------------------------------------
// Helpers
// ---------------------------------------------------------------------------
__device__ __forceinline__ uint32_t smem_to_u32(const void* p) {
    uint32_t a;
    asm("{ .reg .u64 t; cvta.to.shared.u64 t, %1; cvt.u32.u64 %0, t; }" : "=r"(a) : "l"(p));
    return a;
}
__device__ __forceinline__ void cp16(uint32_t dst, const void* src) {
    asm volatile("cp.async.cg.shared.global [%0], [%1], 16;" :: "r"(dst), "l"(src));
}
#define CP_COMMIT() asm volatile("cp.async.commit_group;")
#define CP_WAIT1()  asm volatile("cp.async.wait_group 1;")

__device__ __forceinline__ void ldmx4(uint32_t* r, uint32_t addr) {
    asm volatile("ldmatrix.sync.aligned.m8n8.x4.shared.b16 {%0,%1,%2,%3}, [%4];"
                 : "=r"(r[0]), "=r"(r[1]), "=r"(r[2]), "=r"(r[3]) : "r"(addr));
}
__device__ __forceinline__ void mma16816(float* c, const uint32_t* a, const uint32_t* b) {
    asm volatile("mma.sync.aligned.m16n8k16.row.col.f32.bf16.bf16.f32 "
                 "{%0,%1,%2,%3}, {%4,%5,%6,%7}, {%8,%9}, {%0,%1,%2,%3};"
                 : "+f"(c[0]), "+f"(c[1]), "+f"(c[2]), "+f"(c[3])
                 : "r"(a[0]), "r"(a[1]), "r"(a[2]), "r"(a[3]), "r"(b[0]), "r"(b[1]));
}
__device__ __forceinline__ void split_pair(float x0, float x1, uint32_t& hi, uint32_t& lo) {
    __nv_bfloat162 h = __floats2bfloat162_rn(x0, x1);
    float r0 = x0 - __bfloat162float(h.x);
    float r1 = x1 - __bfloat162float(h.y);
    __nv_bfloat162 l = __floats2bfloat162_rn(r0, r1);
    hi = *(uint32_t*)&h;
    lo = *(uint32_t*)&l;
}
// XOR-swizzled offset inside a (rows x 16 bf16) tile with 128-row subtiles
__device__ __forceinline__ uint32_t swz(int row, int seg) {
    return (row >> 7) * 4096 + (row & 127) * 32 + ((seg << 4) ^ ((row & 4) << 2));
}

// ---------------------------------------------------------------------------
// Pre-pass: split fp32 -> bf16 hi/lo
// ---------------------------------------------------------------------------
__global__ void split_kernel(const float* __restrict__ in,
                             __nv_bfloat16* __restrict__ hi,
                             __nv_bfloat16* __restrict__ lo)
{
    int idx = blockIdx.x * blockDim.x + threadIdx.x;
    float4 v = ((const float4*)in)[idx];
    uint32_t h0, l0, h1, l1;
    split_pair(v.x, v.y, h0, l0);
    split_pair(v.z, v.w, h1, l1);
    ((uint2*)hi)[idx] = make_uint2(h0, h1);
    ((uint2*)lo)[idx] = make_uint2(l0, l1);
}

// ---------------------------------------------------------------------------
// Tensor-core GEMM: C = A[M,K] * B[N,K]^T, operands pre-split bf16 hi/lo
// 128x128 CTA tile, 8 warps (2x4), warp tile 64x32, 2 CTAs/SM
//   MODE 0: proj+bias -> hi/lo out     MODE 1: V-proj -> Vt hi/lo scatter
//   MODE 4: proj+bias -> fp32
// ---------------------------------------------------------------------------
template<int MODE>
__global__ void __launch_bounds__(256, 2)
mma_gemm(const __nv_bfloat16* __restrict__ Ah, const __nv_bfloat16* __restrict__ Al,
         const __nv_bfloat16* __restrict__ Bh, const __nv_bfloat16* __restrict__ Bl,
         const float* __restrict__ bias,
         float* __restrict__ Cf, __nv_bfloat16* __restrict__ Ch,
         __nv_bfloat16* __restrict__ Cl, int K, int lda, int ldb, int ldc)
{
    __shared__ __align__(16) char smem[SMEM_BYTES];
    const int tid = threadIdx.x;
    const int wid = tid >> 5;
    const int lane = tid & 31;
    const int g = lane >> 2, ti = lane & 3;
    const int mwb = (wid >> 2) * 64;
    const int nwb = (wid & 3) * 32;
    const uint32_t sbase = smem_to_u32(smem);

    const int m0 = blockIdx.y * 128;
    const int n0 = blockIdx.x * 128;
    const __nv_bfloat16* pAh = Ah;
    const __nv_bfloat16* pAl = Al;
    const __nv_bfloat16* pBh = Bh;
    const __nv_bfloat16* pBl = Bl;

    const int crow = tid >> 1;
    const int cseg = tid & 1;
    const size_t asrc = (size_t)(m0 + crow) * lda + cseg * 8;
    const size_t bsrc = (size_t)(n0 + crow) * ldb + cseg * 8;
    const uint32_t cdst = swz(crow, cseg);

    const int nchunk = K / BK;

    auto issue = [&](int c) {
        const uint32_t st = sbase + (c % NSTAGE) * STAGE_B;
        const int kt = c * BK;
        cp16(st + cdst,              pAh + asrc + kt);
        cp16(st + cdst + TILE_B,     pAl + asrc + kt);
        cp16(st + cdst + 2*TILE_B,   pBh + bsrc + kt);
        cp16(st + cdst + 3*TILE_B,   pBl + bsrc + kt);
    };

    float acc[4][4][4];
#pragma unroll
    for (int i = 0; i < 4; i++)
#pragma unroll
        for (int j = 0; j < 4; j++)
#pragma unroll
            for (int q = 0; q < 4; q++) acc[i][j][q] = 0.f;

    issue(0); CP_COMMIT();
    if (nchunk > 1) issue(1);
    CP_COMMIT();

    const int arow = lane & 15;
    const int aseg = lane >> 4;
    const int brow = (lane & 7) + ((lane >> 4) << 3);
    const int bseg = (lane >> 3) & 1;

    for (int c = 0; c < nchunk; c++) {
        CP_WAIT1();
        __syncthreads();
        if (c + 2 < nchunk) issue(c + 2);
        CP_COMMIT();

        const uint32_t sbuf = sbase + (c % NSTAGE) * STAGE_B;
        uint32_t ah[4][4], al[4][4];
#pragma unroll
        for (int mf = 0; mf < 4; mf++) {
            uint32_t ad = sbuf + swz(mwb + mf * 16 + arow, aseg);
            ldmx4(ah[mf], ad);
            ldmx4(al[mf], ad + TILE_B);
        }
#pragma unroll
        for (int np = 0; np < 2; np++) {
            uint32_t rh[4], rl[4];
            uint32_t bd = sbuf + 2*TILE_B + swz(nwb + np * 16 + brow, bseg);
            ldmx4(rh, bd);
            ldmx4(rl, bd + TILE_B);
#pragma unroll
            for (int mf = 0; mf < 4; mf++) {
                mma16816(acc[mf][2*np],   ah[mf], rh);
                mma16816(acc[mf][2*np+1], ah[mf], rh + 2);
                mma16816(acc[mf][2*np],   ah[mf], rl);
                mma16816(acc[mf][2*np+1], ah[mf], rl + 2);
                mma16816(acc[mf][2*np],   al[mf], rh);
                mma16816(acc[mf][2*np+1], al[mf], rh + 2);
            }
        }
    }
    __syncthreads();

    // Epilogue: two passes through fp32 SMEM stage -> coalesced stores
    float* stage = (float*)smem;
#pragma unroll
    for (int p = 0; p < 2; p++) {
        if (p) __syncthreads();
#pragma unroll
        for (int mf = 0; mf < 4; mf++)
#pragma unroll
            for (int e = 0; e < 2; e++) {
                const int nf = 2 * p + e;
                const int row = mwb + mf * 16 + g;
                const int cm = (wid & 3) * 16 + e * 8 + ti * 2;
                *(float2*)&stage[row * STAGE_PITCH + cm] =
                    make_float2(acc[mf][nf][0], acc[mf][nf][1]);
                *(float2*)&stage[(row + 8) * STAGE_PITCH + cm] =
                    make_float2(acc[mf][nf][2], acc[mf][nf][3]);
            }
        __syncthreads();
#pragma unroll
        for (int it = 0; it < 8; it++) {
            const int lin = it * 1024 + tid * 4;
            const int row = lin >> 6;
            const int cm = lin & 63;
            const int col = ((cm >> 4) << 5) + (p << 4) + (cm & 15);
            float4 v = *(float4*)&stage[row * STAGE_PITCH + cm];
            if (MODE == 0 || MODE == 1) {
                float b0, b1, b2, b3;
                size_t off;
                if (MODE == 0) {
                    float4 b4 = *(const float4*)(bias + n0 + col);
                    b0 = b4.x; b1 = b4.y; b2 = b4.z; b3 = b4.w;
                    off = (size_t)(m0 + row) * ldc + n0 + col;
                } else {
                    const int gr = m0 + row;             // feature = h*128+d
                    const int h = gr >> 7, d = gr & 127;
                    const int n = n0 + col;              // b*256+t
                    const int b = n >> 8, t = n & 255;
                    b0 = b1 = b2 = b3 = bias[gr];
                    off = ((size_t)(b * NHEAD + h) * HD_DIM + d) * T_DIM + t;
                }
                uint32_t h0, l0, h1, l1;
                split_pair(v.x + b0, v.y + b1, h0, l0);
                split_pair(v.z + b2, v.w + b3, h1, l1);
                *(uint2*)(Ch + off) = make_uint2(h0, h1);
                *(uint2*)(Cl + off) = make_uint2(l0, l1);
            } else {  // MODE 4: fp32 + bias
                float4 b4 = *(const float4*)(bias + n0 + col);
                float4 o = make_float4(v.x + b4.x, v.y + b4.y, v.z + b4.z, v.w + b4.w);
                *(float4*)(Cf + (size_t)(m0 + row) * ldc + n0 + col) = o;
            }
        }
    }
}

// ---------------------------------------------------------------------------
// Fused attention: per (b,h), 128 q-rows x full T=256.
//  phase 1: S = clip(QK^T/sqrt(d)) masked  (warp tile 64x64)
//  phase 2: softmax in registers
//  phase 3: stage P hi/lo into SMEM A-operand tiles (16 chunks of 128x16)
//  phase 4: ctx = P @ Vt^T (warp tile 64x32, V streamed via cp.async)
//  phase 5: ctx scatter -> Ch/Cl [b*S+s, h*128+d]
// ---------------------------------------------------------------------------
__global__ void __launch_bounds__(256, 1)
fused_attn_kernel(const __nv_bfloat16* __restrict__ Qh, const __nv_bfloat16* __restrict__ Ql,
                  const __nv_bfloat16* __restrict__ Kh, const __nv_bfloat16* __restrict__ Kl,
                  const __nv_bfloat16* __restrict__ Vth, const __nv_bfloat16* __restrict__ Vtl,
                  const int* __restrict__ mask,
                  __nv_bfloat16* __restrict__ Ch, __nv_bfloat16* __restrict__ Cl)
{
    extern __shared__ __align__(16) char dsm[];
    __shared__ float red[128][4];
    __shared__ int smask[T_DIM];

    const int tid = threadIdx.x;
    const int wid = tid >> 5;
    const int lane = tid & 31;
    const int g = lane >> 2, ti = lane & 3;
    const int mwb = (wid >> 2) * 64;
    const int nwb = (wid & 3) * 64;       // scores-phase n offset
    const uint32_t sbase = smem_to_u32(dsm);

    const int m0 = blockIdx.y * 128;
    const int z = blockIdx.z;
    const int bb = z >> 4, hh = z & 15;
    const __nv_bfloat16* pQh = Qh + (size_t)bb * S_DIM * H_DIM + hh * HD_DIM;
    const __nv_bfloat16* pQl = Ql + (size_t)bb * S_DIM * H_DIM + hh * HD_DIM;
    const __nv_bfloat16* pKh = Kh + (size_t)bb * T_DIM * H_DIM + hh * HD_DIM;
    const __nv_bfloat16* pKl = Kl + (size_t)bb * T_DIM * H_DIM + hh * HD_DIM;

    smask[tid] = mask[bb * T_DIM + tid];   // blockDim == T_DIM == 256

    const int crow = tid >> 1, cseg = tid & 1;
    const size_t qsrc  = (size_t)(m0 + crow) * H_DIM + cseg * 8;
    const size_t ksrc0 = (size_t)crow * H_DIM + cseg * 8;
    const size_t ksrc1 = (size_t)(crow + 128) * H_DIM + cseg * 8;
    const uint32_t adst = swz(crow, cseg);
    const uint32_t bdst0 = swz(crow, cseg);
    const uint32_t bdst1 = swz(crow + 128, cseg);

    auto issue = [&](int c) {
        const uint32_t st = sbase + (c % 3) * SS_STAGE;
        const int kt = c * BK;
        cp16(st + adst,                       pQh + qsrc + kt);
        cp16(st + adst + SS_ATB,              pQl + qsrc + kt);
        cp16(st + 2*SS_ATB + bdst0,           pKh + ksrc0 + kt);
        cp16(st + 2*SS_ATB + bdst1,           pKh + ksrc1 + kt);
        cp16(st + 2*SS_ATB + SS_BTB + bdst0,  pKl + ksrc0 + kt);
        cp16(st + 2*SS_ATB + SS_BTB + bdst1,  pKl + ksrc1 + kt);
    };

    float acc[4][8][4];
#pragma unroll
    for (int i = 0; i < 4; i++)
#pragma unroll
        for (int j = 0; j < 8; j++)
#pragma unroll
            for (int q = 0; q < 4; q++) acc[i][j][q] = 0.f;

    issue(0); CP_COMMIT();
    issue(1); CP_COMMIT();

    const int arow = lane & 15;
    const int aseg = lane >> 4;
    const int brow = (lane & 7) + ((lane >> 4) << 3);
    const int bseg = (lane >> 3) & 1;

    for (int c = 0; c < 8; c++) {          // K = HD = 128
        CP_WAIT1();
        __syncthreads();
        if (c + 2 < 8) issue(c + 2);
        CP_COMMIT();

        const uint32_t sbuf = sbase + (c % 3) * SS_STAGE;
        uint32_t ah[4][4], al[4][4];
#pragma unroll
        for (int mf = 0; mf < 4; mf++) {
            uint32_t ad = sbuf + swz(mwb + mf * 16 + arow, aseg);
            ldmx4(ah[mf], ad);
            ldmx4(al[mf], ad + SS_ATB);
        }
#pragma unroll
        for (int np = 0; np < 4; np++) {
            uint32_t rh[4], rl[4];
            uint32_t bd = sbuf + 2*SS_ATB + swz(nwb + np * 16 + brow, bseg);
            ldmx4(rh, bd);
            ldmx4(rl, bd + SS_BTB);
#pragma unroll
            for (int mf = 0; mf < 4; mf++) {
                mma16816(acc[mf][2*np],   ah[mf], rh);
                mma16816(acc[mf][2*np+1], ah[mf], rh + 2);
                mma16816(acc[mf][2*np],   ah[mf], rl);
                mma16816(acc[mf][2*np+1], ah[mf], rl + 2);
                mma16816(acc[mf][2*np],   al[mf], rh);
                mma16816(acc[mf][2*np+1], al[mf], rh + 2);
            }
        }
    }
    __syncthreads();

    // ---- mask/scale/clip + per-row softmax (rows span 4 n-warps) ----
    const float invs = 0.08838834764831845f;   // 1/sqrt(128)
    float rmax[4][2], rsum[4][2];
#pragma unroll
    for (int mf = 0; mf < 4; mf++) {
        float mx0 = -1e30f, mx1 = -1e30f;
#pragma unroll
        for (int nf = 0; nf < 8; nf++) {
            const int col = nwb + nf * 8 + ti * 2;
            const bool k0 = smask[col] != 0;
            const bool k1 = smask[col + 1] != 0;
            float* a = acc[mf][nf];
            a[0] = k0 ? fminf(fmaxf(a[0] * invs, -50.f), 50.f) : -50.f;
            a[1] = k1 ? fminf(fmaxf(a[1] * invs, -50.f), 50.f) : -50.f;
            a[2] = k0 ? fminf(fmaxf(a[2] * invs, -50.f), 50.f) : -50.f;
            a[3] = k1 ? fminf(fmaxf(a[3] * invs, -50.f), 50.f) : -50.f;
            mx0 = fmaxf(mx0, fmaxf(a[0], a[1]));
            mx1 = fmaxf(mx1, fmaxf(a[2], a[3]));
        }
        mx0 = fmaxf(mx0, __shfl_xor_sync(0xffffffffu, mx0, 1));
        mx0 = fmaxf(mx0, __shfl_xor_sync(0xffffffffu, mx0, 2));
        mx1 = fmaxf(mx1, __shfl_xor_sync(0xffffffffu, mx1, 1));
        mx1 = fmaxf(mx1, __shfl_xor_sync(0xffffffffu, mx1, 2));
        if (ti == 0) {
            red[mwb + mf * 16 + g][wid & 3]     = mx0;
            red[mwb + mf * 16 + g + 8][wid & 3] = mx1;
        }
    }
    __syncthreads();
#pragma unroll
    for (int mf = 0; mf < 4; mf++) {
        float4 r0 = *(float4*)red[mwb + mf * 16 + g];
        rmax[mf][0] = fmaxf(fmaxf(r0.x, r0.y), fmaxf(r0.z, r0.w));
        float4 r1 = *(float4*)red[mwb + mf * 16 + g + 8];
        rmax[mf][1] = fmaxf(fmaxf(r1.x, r1.y), fmaxf(r1.z, r1.w));
    }
    __syncthreads();
#pragma unroll
    for (int mf = 0; mf < 4; mf++) {
        float s0 = 0.f, s1 = 0.f;
#pragma unroll
        for (int nf = 0; nf < 8; nf++) {
            float* a = acc[mf][nf];
            a[0] = __expf(a[0] - rmax[mf][0]); s0 += a[0];
            a[1] = __expf(a[1] - rmax[mf][0]); s0 += a[1];
            a[2] = __expf(a[2] - rmax[mf][1]); s1 += a[2];
            a[3] = __expf(a[3] - rmax[mf][1]); s1 += a[3];
        }
        s0 += __shfl_xor_sync(0xffffffffu, s0, 1);
        s0 += __shfl_xor_sync(0xffffffffu, s0, 2);
        s1 += __shfl_xor_sync(0xffffffffu, s1, 1);
        s1 += __shfl_xor_sync(0xffffffffu, s1, 2);
        if (ti == 0) {
            red[mwb + mf * 16 + g][wid & 3]     = s0;
            red[mwb + mf * 16 + g + 8][wid & 3] = s1;
        }
    }
    __syncthreads();
#pragma unroll
    for (int mf = 0; mf < 4; mf++) {
        float4 r0 = *(float4*)red[mwb + mf * 16 + g];
        rsum[mf][0] = 1.f / (r0.x + r0.y + r0.z + r0.w);
        float4 r1 = *(float4*)red[mwb + mf * 16 + g + 8];
        rsum[mf][1] = 1.f / (r1.x + r1.y + r1.z + r1.w);
    }

    // ---- stage P hi/lo into SMEM A-operand tiles (chunk c: hi at c*8192, lo +4096) ----
#pragma unroll
    for (int mf = 0; mf < 4; mf++) {
        const int r0 = mwb + mf * 16 + g;
#pragma unroll
        for (int nf = 0; nf < 8; nf++) {
            const int col = nwb + nf * 8 + ti * 2;
            const int ch = col >> 4;
            const int colc = col & 15;
            const uint32_t cb = ch * 8192 + (((colc >> 3) << 4) ^ ((r0 & 4) << 2))
                              + (colc & 7) * 2 + r0 * 32;
            float* a = acc[mf][nf];
            uint32_t h0, l0, h1, l1;
            split_pair(a[0] * rsum[mf][0], a[1] * rsum[mf][0], h0, l0);
            split_pair(a[2] * rsum[mf][1], a[3] * rsum[mf][1], h1, l1);
            *(uint32_t*)(dsm + cb)               = h0;
            *(uint32_t*)(dsm + cb + 4096)        = l0;
            *(uint32_t*)(dsm + cb + 256)         = h1;   // row r0+8: same swizzle bit
            *(uint32_t*)(dsm + cb + 256 + 4096)  = l1;
        }
    }
    __syncthreads();

    // ---- PV mainloop: ctx[128 s][128 d], K = T = 256, 16 chunks, V streamed ----
    const __nv_bfloat16* pVh = Vth + (size_t)z * HD_DIM * T_DIM;
    const __nv_bfloat16* pVl = Vtl + (size_t)z * HD_DIM * T_DIM;
    const size_t vsrc = (size_t)crow * T_DIM + cseg * 8;
    const uint32_t vdst = swz(crow, cseg);
    auto issueV = [&](int c) {
        const uint32_t st = sbase + VOFF + (c % 3) * 8192;
        cp16(st + vdst,        pVh + vsrc + c * 16);
        cp16(st + vdst + 4096, pVl + vsrc + c * 16);
    };

    float ctx[4][4][4];
#pragma unroll
    for (int i = 0; i < 4; i++)
#pragma unroll
        for (int j = 0; j < 4; j++)
#pragma unroll
            for (int q = 0; q < 4; q++) ctx[i][j][q] = 0.f;

    issueV(0); CP_COMMIT();
    issueV(1); CP_COMMIT();

    const int nwb2 = (wid & 3) * 32;      // ctx-phase n offset (d)
    for (int c = 0; c < 16; c++) {
        CP_WAIT1();
        __syncthreads();
        if (c + 2 < 16) issueV(c + 2);
        CP_COMMIT();

        const uint32_t pbuf = sbase + c * 8192;
        const uint32_t vbuf = sbase + VOFF + (c % 3) * 8192;
        uint32_t ah[4][4], al[4][4];
#pragma unroll
        for (int mf = 0; mf < 4; mf++) {
            uint32_t ad = pbuf + swz(mwb + mf * 16 + arow, aseg);
            ldmx4(ah[mf], ad);
            ldmx4(al[mf], ad + 4096);
        }
#pragma unroll
        for (int np = 0; np < 2; np++) {
            uint32_t rh[4], rl[4];
            uint32_t bd = vbuf + swz(nwb2 + np * 16 + brow, bseg);
            ldmx4(rh, bd);
            ldmx4(rl, bd + 4096);
#pragma unroll
            for (int mf = 0; mf < 4; mf++) {
                mma16816(ctx[mf][2*np],   ah[mf], rh);
                mma16816(ctx[mf][2*np+1], ah[mf], rh + 2);
                mma16816(ctx[mf][2*np],   ah[mf], rl);
                mma16816(ctx[mf][2*np+1], ah[mf], rl + 2);
                mma16816(ctx[mf][2*np],   al[mf], rh);
                mma16816(ctx[mf][2*np+1], al[mf], rh + 2);
            }
        }
    }
    __syncthreads();

    // ---- ctx scatter epilogue -> Ch/Cl [b*S+s, h*128+d] ----
    float* stage = (float*)dsm;
#pragma unroll
    for (int p = 0; p < 2; p++) {
        if (p) __syncthreads();
#pragma unroll
        for (int mf = 0; mf < 4; mf++)
#pragma unroll
            for (int e = 0; e < 2; e++) {
                const int nf = 2 * p + e;
                const int row = mwb + mf * 16 + g;
                const int cm = (wid & 3) * 16 + e * 8 + ti * 2;
                *(float2*)&stage[row * STAGE_PITCH + cm] =
                    make_float2(ctx[mf][nf][0], ctx[mf][nf][1]);
                *(float2*)&stage[(row + 8) * STAGE_PITCH + cm] =
                    make_float2(ctx[mf][nf][2], ctx[mf][nf][3]);
            }
        __syncthreads();
#pragma unroll
        for (int it = 0; it < 8; it++) {
            const int lin = it * 1024 + tid * 4;
            const int row = lin >> 6;
            const int cm = lin & 63;
            const int col = ((cm >> 4) << 5) + (p << 4) + (cm & 15);
            float4 v = *(float4*)&stage[row * STAGE_PITCH + cm];
            uint32_t h0, l0, h1, l1;
            split_pair(v.x, v.y, h0, l0);
            split_pair(v.z, v.w, h1, l1);
            size_t off = (size_t)(bb * S_DIM + m0 + row) * H_DIM + hh * HD_DIM + col;
            *(uint2*)(Ch + off) = make_uint2(h0, h1);
            *(uint2*)(Cl + off) = make_uint2(l0, l1);
        }
    }
}

// ---------------------------------------------------------------------------
// LayerNorm (residual_scale applied), one block per row
// ---------------------------------------------------------------------------
__device__ __forceinline__ float block_sum(float v)
{
    __shared__ float red[8];
#pragma unroll
    for (int o = 16; o; o >>= 1) v += __shfl_xor_sync(0xffffffffu, v, o);
    int w = threadIdx.x >> 5;
    if ((threadIdx.x & 31) == 0) red[w] = v;
    __syncthreads();
    float t = (threadIdx.x < 8) ? red[threadIdx.x] : 0.f;
    if (threadIdx.x < 32) {
#pragma unroll
        for (int o = 4; o; o >>= 1) t += __shfl_xor_sync(0xffffffffu, t, o);
        if (threadIdx.x == 0) red[0] = t;
    }
    __syncthreads();
    float r = red[0];
    __syncthreads();
    return r;
}

__global__ void ln_kernel(const float* __restrict__ D, const float* __restrict__ gamma,
                          const float* __restrict__ beta, const float* __restrict__ rsp,
                          float* __restrict__ out)
{
    int row = blockIdx.x;
    int tid = threadIdx.x;
    float rs = fminf(fmaxf(rsp[0], 0.f), 0.3f);

    const float* d = D + (size_t)row * H_DIM;
    float4 u0 = *(const float4*)(d + tid * 4);
    float4 u1 = *(const float4*)(d + 1024 + tid * 4);
    float x[8] = {rs*u0.x, rs*u0.y, rs*u0.z, rs*u0.w,
                  rs*u1.x, rs*u1.y, rs*u1.z, rs*u1.w};

    float ps = 0.f;
#pragma unroll
    for (int i = 0; i < 8; i++) ps += x[i];
    float mean = block_sum(ps) * (1.f / 2048.f);

    float pv = 0.f;
#pragma unroll
    for (int i = 0; i < 8; i++) { float dd = x[i] - mean; pv += dd * dd; }
    float var = block_sum(pv) * (1.f / 2048.f);
    float inv = rsqrtf(var + 1e-5f);

    float4 gz0 = *(const float4*)(gamma + tid * 4);
    float4 gz1 = *(const float4*)(gamma + 1024 + tid * 4);
    float4 bz0 = *(const float4*)(beta + tid * 4);
    float4 bz1 = *(const float4*)(beta + 1024 + tid * 4);

    float* o = out + (size_t)row * H_DIM;
    *(float4*)(o + tid * 4) = make_float4(
        (x[0]-mean)*inv*gz0.x + bz0.x, (x[1]-mean)*inv*gz0.y + bz0.y,
        (x[2]-mean)*inv*gz0.z + bz0.z, (x[3]-mean)*inv*gz0.w + bz0.w);
    *(float4*)(o + 1024 + tid * 4) = make_float4(
        (x[4]-mean)*inv*gz1.x + bz1.x, (x[5]-mean)*inv*gz1.y + bz1.y,
        (x[6]-mean)*inv*gz1.z + bz1.z, (x[7]-mean)*inv*gz1.w + bz1.w);
}

// ---------------------------------------------------------------------------
// Launch
// ---------------------------------------------------------------------------
extern "C" void kernel_launch(void* const* d_in, const int* in_sizes, int n_in,
                              void* d_out, int out_size)
{
    const float* hs    = (const float*)d_in[0];
    const float* at    = (const float*)d_in[1];
    const int*   mask  = (const int*)  d_in[2];
    const float* Wq    = (const float*)d_in[3];
    const float* bq    = (const float*)d_in[4];
    const float* Wk    = (const float*)d_in[5];
    const float* bk    = (const float*)d_in[6];
    const float* Wv    = (const float*)d_in[7];
    const float* bv    = (const float*)d_in[8];
    const float* Wo    = (const float*)d_in[9];
    const float* bo    = (const float*)d_in[10];
    const float* gamma = (const float*)d_in[11];
    const float* beta  = (const float*)d_in[12];
    const float* rsp   = (const float*)d_in[13];
    float* out = (float*)d_out;

    __nv_bfloat16 *hsh, *hsl, *ath, *atl, *Wqh, *Wql, *Wkh, *Wkl, *Wvh, *Wvl, *Woh, *Wol;
    __nv_bfloat16 *Qh, *Ql, *Kh, *Kl, *Vth, *Vtl, *Ch, *Cl;
    float *Db;
    cudaGetSymbolAddress((void**)&hsh, g_hsh); cudaGetSymbolAddress((void**)&hsl, g_hsl);
    cudaGetSymbolAddress((void**)&ath, g_ath); cudaGetSymbolAddress((void**)&atl, g_atl);
    cudaGetSymbolAddress((void**)&Wqh, g_Wqh); cudaGetSymbolAddress((void**)&Wql, g_Wql);
    cudaGetSymbolAddress((void**)&Wkh, g_Wkh); cudaGetSymbolAddress((void**)&Wkl, g_Wkl);
    cudaGetSymbolAddress((void**)&Wvh, g_Wvh); cudaGetSymbolAddress((void**)&Wvl, g_Wvl);
    cudaGetSymbolAddress((void**)&Woh, g_Woh); cudaGetSymbolAddress((void**)&Wol, g_Wol);
    cudaGetSymbolAddress((void**)&Qh,  g_Qh);  cudaGetSymbolAddress((void**)&Ql,  g_Ql);
    cudaGetSymbolAddress((void**)&Kh,  g_Kh);  cudaGetSymbolAddress((void**)&Kl,  g_Kl);
    cudaGetSymbolAddress((void**)&Vth, g_Vth); cudaGetSymbolAddress((void**)&Vtl, g_Vtl);
    cudaGetSymbolAddress((void**)&Ch,  g_Ch);  cudaGetSymbolAddress((void**)&Cl,  g_Cl);
    cudaGetSymbolAddress((void**)&Db,  g_D);

    cudaFuncSetAttribute(fused_attn_kernel,
                         cudaFuncAttributeMaxDynamicSharedMemorySize, SS_SMEM);

    // Pre-pass: split all fp32 operands into bf16 hi/lo
    split_kernel<<<16384, 256>>>(hs, hsh, hsl);
    split_kernel<<<2048,  256>>>(at, ath, atl);
    split_kernel<<<4096,  256>>>(Wq, Wqh, Wql);
    split_kernel<<<4096,  256>>>(Wk, Wkh, Wkl);
    split_kernel<<<4096,  256>>>(Wv, Wvh, Wvl);
    split_kernel<<<4096,  256>>>(Wo, Woh, Wol);

    // Q projection -> Qh/Ql
    mma_gemm<0><<<dim3(16, 64, 1), 256>>>(hsh, hsl, Wqh, Wql, bq,
                                          nullptr, Qh, Ql, 2048, 2048, 2048, 2048);
    // K projection -> Kh/Kl
    mma_gemm<0><<<dim3(16, 8, 1), 256>>>(ath, atl, Wkh, Wkl, bk,
                                         nullptr, Kh, Kl, 2048, 2048, 2048, 2048);
    // V projection (A=Wv, B=at) -> Vt hi/lo [b,h,d,t]
    mma_gemm<1><<<dim3(8, 16, 1), 256>>>(Wvh, Wvl, ath, atl, bv,
                                         nullptr, Vth, Vtl, 2048, 2048, 2048, 0);
    // Fused scores + softmax + PV -> ctx hi/lo
    fused_attn_kernel<<<dim3(1, 16, 64), 256, SS_SMEM>>>(Qh, Ql, Kh, Kl, Vth, Vtl,
                                                         mask, Ch, Cl);
    // O projection -> fp32 D
    mma_gemm<4><<<dim3(16, 64, 1), 256>>>(Ch, Cl, Woh, Wol, bo,
                                          Db, nullptr, nullptr, 2048, 2048, 2048, 2048);
    // residual scale + LayerNorm
    ln_kernel<<<8192, 256>>>(Db, gamma, beta, rsp, out);
}

// round 10
// speedup vs baseline: 1.8327x; 1.3145x over previous
#include <cuda_runtime.h>
#include <cuda_bf16.h>
#include <cuda_fp16.h>
#include <cstdint>
#include <math.h>

#define B_DIM 4
#define S_DIM 2048
#define T_DIM 256
#define H_DIM 2048
#define NHEAD 16
#define HD_DIM 128

// bf16 3-term GEMM: 128x128 tile, BK=16, 3-stage ring, 2 CTAs/SM
#define BK 16
#define TILE_B 4096
#define STAGE_B 16384
#define NSTAGE 3
#define SMEM_BYTES 49152
#define STAGE_PITCH 68

// fp16 2-term GEMM: 128x128 tile, BK=16, 4-stage ring (12KB/stage), 2 CTAs/SM
#define FT 4096
#define FSTG 12288

// Fused attention kernel
#define SS_ATB 4096
#define SS_BTB 8192
#define SS_STAGE 24576
#define VOFF 131072
#define SS_SMEM (VOFF + 3*8192)   // 155648

// ---------------------------------------------------------------------------
// Persistent scratch
// ---------------------------------------------------------------------------
__device__ __half         g_hs16[8192*2048];
__device__ __half         g_Wq16h[2048*2048], g_Wq16l[2048*2048];
__device__ __half         g_Wo16h[2048*2048], g_Wo16l[2048*2048];
__device__ __half         g_C16[8192*2048];
__device__ __nv_bfloat16 g_ath[1024*2048], g_atl[1024*2048];
__device__ __nv_bfloat16 g_Wkh[2048*2048], g_Wkl[2048*2048];
__device__ __nv_bfloat16 g_Wvh[2048*2048], g_Wvl[2048*2048];
__device__ __nv_bfloat16 g_Qh[8192*2048],  g_Ql[8192*2048];
__device__ __nv_bfloat16 g_Kh[1024*2048],  g_Kl[1024*2048];
__device__ __nv_bfloat16 g_Vth[64*128*256], g_Vtl[64*128*256];
__device__ float         g_D[8192*2048];

// ---------------------------------------------------------------------------
// Helpers
// ---------------------------------------------------------------------------
__device__ __forceinline__ uint32_t smem_to_u32(const void* p) {
    uint32_t a;
    asm("{ .reg .u64 t; cvta.to.shared.u64 t, %1; cvt.u32.u64 %0, t; }" : "=r"(a) : "l"(p));
    return a;
}
__device__ __forceinline__ void cp16(uint32_t dst, const void* src) {
    asm volatile("cp.async.cg.shared.global [%0], [%1], 16;" :: "r"(dst), "l"(src));
}
#define CP_COMMIT() asm volatile("cp.async.commit_group;")
#define CP_WAIT1()  asm volatile("cp.async.wait_group 1;")
#define CP_WAIT2()  asm volatile("cp.async.wait_group 2;")

__device__ __forceinline__ void ldmx4(uint32_t* r, uint32_t addr) {
    asm volatile("ldmatrix.sync.aligned.m8n8.x4.shared.b16 {%0,%1,%2,%3}, [%4];"
                 : "=r"(r[0]), "=r"(r[1]), "=r"(r[2]), "=r"(r[3]) : "r"(addr));
}
__device__ __forceinline__ void mma16816(float* c, const uint32_t* a, const uint32_t* b) {
    asm volatile("mma.sync.aligned.m16n8k16.row.col.f32.bf16.bf16.f32 "
                 "{%0,%1,%2,%3}, {%4,%5,%6,%7}, {%8,%9}, {%0,%1,%2,%3};"
                 : "+f"(c[0]), "+f"(c[1]), "+f"(c[2]), "+f"(c[3])
                 : "r"(a[0]), "r"(a[1]), "r"(a[2]), "r"(a[3]), "r"(b[0]), "r"(b[1]));
}
__device__ __forceinline__ void mma16816h(float* c, const uint32_t* a, const uint32_t* b) {
    asm volatile("mma.sync.aligned.m16n8k16.row.col.f32.f16.f16.f32 "
                 "{%0,%1,%2,%3}, {%4,%5,%6,%7}, {%8,%9}, {%0,%1,%2,%3};"
                 : "+f"(c[0]), "+f"(c[1]), "+f"(c[2]), "+f"(c[3])
                 : "r"(a[0]), "r"(a[1]), "r"(a[2]), "r"(a[3]), "r"(b[0]), "r"(b[1]));
}
__device__ __forceinline__ void split_pair(float x0, float x1, uint32_t& hi, uint32_t& lo) {
    __nv_bfloat162 h = __floats2bfloat162_rn(x0, x1);
    float r0 = x0 - __bfloat162float(h.x);
    float r1 = x1 - __bfloat162float(h.y);
    __nv_bfloat162 l = __floats2bfloat162_rn(r0, r1);
    hi = *(uint32_t*)&h;
    lo = *(uint32_t*)&l;
}
__device__ __forceinline__ void split_pair_f16(float x0, float x1, uint32_t& hi, uint32_t& lo) {
    __half2 h = __floats2half2_rn(x0, x1);
    float r0 = x0 - __half2float(__low2half(h));
    float r1 = x1 - __half2float(__high2half(h));
    __half2 l = __floats2half2_rn(r0, r1);
    hi = *(uint32_t*)&h;
    lo = *(uint32_t*)&l;
}
__device__ __forceinline__ uint32_t swz(int row, int seg) {
    return (row >> 7) * 4096 + (row & 127) * 32 + ((seg << 4) ^ ((row & 4) << 2));
}

// ---------------------------------------------------------------------------
// Pre-pass kernels
// ---------------------------------------------------------------------------
__global__ void split_kernel(const float* __restrict__ in,
                             __nv_bfloat16* __restrict__ hi,
                             __nv_bfloat16* __restrict__ lo)
{
    int idx = blockIdx.x * blockDim.x + threadIdx.x;
    float4 v = ((const float4*)in)[idx];
    uint32_t h0, l0, h1, l1;
    split_pair(v.x, v.y, h0, l0);
    split_pair(v.z, v.w, h1, l1);
    ((uint2*)hi)[idx] = make_uint2(h0, h1);
    ((uint2*)lo)[idx] = make_uint2(l0, l1);
}
__global__ void split16_kernel(const float* __restrict__ in,
                               __half* __restrict__ hi, __half* __restrict__ lo)
{
    int idx = blockIdx.x * blockDim.x + threadIdx.x;
    float4 v = ((const float4*)in)[idx];
    uint32_t h0, l0, h1, l1;
    split_pair_f16(v.x, v.y, h0, l0);
    split_pair_f16(v.z, v.w, h1, l1);
    ((uint2*)hi)[idx] = make_uint2(h0, h1);
    ((uint2*)lo)[idx] = make_uint2(l0, l1);
}
__global__ void cast16_kernel(const float* __restrict__ in, __half* __restrict__ out)
{
    int idx = blockIdx.x * blockDim.x + threadIdx.x;
    float4 v = ((const float4*)in)[idx];
    __half2 a = __floats2half2_rn(v.x, v.y);
    __half2 b = __floats2half2_rn(v.z, v.w);
    ((uint2*)out)[idx] = make_uint2(*(uint32_t*)&a, *(uint32_t*)&b);
}

// ---------------------------------------------------------------------------
// bf16 3-term GEMM (unchanged from R9): MODE 0 proj->bf16 pair, MODE 1 V-scatter
// ---------------------------------------------------------------------------
template<int MODE>
__global__ void __launch_bounds__(256, 2)
mma_gemm(const __nv_bfloat16* __restrict__ Ah, const __nv_bfloat16* __restrict__ Al,
         const __nv_bfloat16* __restrict__ Bh, const __nv_bfloat16* __restrict__ Bl,
         const float* __restrict__ bias,
         __nv_bfloat16* __restrict__ Ch, __nv_bfloat16* __restrict__ Cl,
         int K, int lda, int ldb, int ldc)
{
    __shared__ __align__(16) char smem[SMEM_BYTES];
    const int tid = threadIdx.x;
    const int wid = tid >> 5;
    const int lane = tid & 31;
    const int g = lane >> 2, ti = lane & 3;
    const int mwb = (wid >> 2) * 64;
    const int nwb = (wid & 3) * 32;
    const uint32_t sbase = smem_to_u32(smem);

    const int m0 = blockIdx.y * 128;
    const int n0 = blockIdx.x * 128;

    const int crow = tid >> 1;
    const int cseg = tid & 1;
    const size_t asrc = (size_t)(m0 + crow) * lda + cseg * 8;
    const size_t bsrc = (size_t)(n0 + crow) * ldb + cseg * 8;
    const uint32_t cdst = swz(crow, cseg);

    const int nchunk = K / BK;

    auto issue = [&](int c) {
        const uint32_t st = sbase + (c % NSTAGE) * STAGE_B;
        const int kt = c * BK;
        cp16(st + cdst,              Ah + asrc + kt);
        cp16(st + cdst + TILE_B,     Al + asrc + kt);
        cp16(st + cdst + 2*TILE_B,   Bh + bsrc + kt);
        cp16(st + cdst + 3*TILE_B,   Bl + bsrc + kt);
    };

    float acc[4][4][4];
#pragma unroll
    for (int i = 0; i < 4; i++)
#pragma unroll
        for (int j = 0; j < 4; j++)
#pragma unroll
            for (int q = 0; q < 4; q++) acc[i][j][q] = 0.f;

    issue(0); CP_COMMIT();
    issue(1); CP_COMMIT();

    const int arow = lane & 15;
    const int aseg = lane >> 4;
    const int brow = (lane & 7) + ((lane >> 4) << 3);
    const int bseg = (lane >> 3) & 1;

    for (int c = 0; c < nchunk; c++) {
        CP_WAIT1();
        __syncthreads();
        if (c + 2 < nchunk) issue(c + 2);
        CP_COMMIT();

        const uint32_t sbuf = sbase + (c % NSTAGE) * STAGE_B;
        uint32_t ah[4][4], al[4][4];
#pragma unroll
        for (int mf = 0; mf < 4; mf++) {
            uint32_t ad = sbuf + swz(mwb + mf * 16 + arow, aseg);
            ldmx4(ah[mf], ad);
            ldmx4(al[mf], ad + TILE_B);
        }
#pragma unroll
        for (int np = 0; np < 2; np++) {
            uint32_t rh[4], rl[4];
            uint32_t bd = sbuf + 2*TILE_B + swz(nwb + np * 16 + brow, bseg);
            ldmx4(rh, bd);
            ldmx4(rl, bd + TILE_B);
#pragma unroll
            for (int mf = 0; mf < 4; mf++) {
                mma16816(acc[mf][2*np],   ah[mf], rh);
                mma16816(acc[mf][2*np+1], ah[mf], rh + 2);
                mma16816(acc[mf][2*np],   ah[mf], rl);
                mma16816(acc[mf][2*np+1], ah[mf], rl + 2);
                mma16816(acc[mf][2*np],   al[mf], rh);
                mma16816(acc[mf][2*np+1], al[mf], rh + 2);
            }
        }
    }
    __syncthreads();

    float* stage = (float*)smem;
#pragma unroll
    for (int p = 0; p < 2; p++) {
        if (p) __syncthreads();
#pragma unroll
        for (int mf = 0; mf < 4; mf++)
#pragma unroll
            for (int e = 0; e < 2; e++) {
                const int nf = 2 * p + e;
                const int row = mwb + mf * 16 + g;
                const int cm = (wid & 3) * 16 + e * 8 + ti * 2;
                *(float2*)&stage[row * STAGE_PITCH + cm] =
                    make_float2(acc[mf][nf][0], acc[mf][nf][1]);
                *(float2*)&stage[(row + 8) * STAGE_PITCH + cm] =
                    make_float2(acc[mf][nf][2], acc[mf][nf][3]);
            }
        __syncthreads();
#pragma unroll
        for (int it = 0; it < 8; it++) {
            const int lin = it * 1024 + tid * 4;
            const int row = lin >> 6;
            const int cm = lin & 63;
            const int col = ((cm >> 4) << 5) + (p << 4) + (cm & 15);
            float4 v = *(float4*)&stage[row * STAGE_PITCH + cm];
            float b0, b1, b2, b3;
            size_t off;
            if (MODE == 0) {
                float4 b4 = *(const float4*)(bias + n0 + col);
                b0 = b4.x; b1 = b4.y; b2 = b4.z; b3 = b4.w;
                off = (size_t)(m0 + row) * ldc + n0 + col;
            } else {
                const int gr = m0 + row;             // feature = h*128+d
                const int h = gr >> 7, d = gr & 127;
                const int n = n0 + col;              // b*256+t
                const int b = n >> 8, t = n & 255;
                b0 = b1 = b2 = b3 = bias[gr];
                off = ((size_t)(b * NHEAD + h) * HD_DIM + d) * T_DIM + t;
            }
            uint32_t h0, l0, h1, l1;
            split_pair(v.x + b0, v.y + b1, h0, l0);
            split_pair(v.z + b2, v.w + b3, h1, l1);
            *(uint2*)(Ch + off) = make_uint2(h0, h1);
            *(uint2*)(Cl + off) = make_uint2(l0, l1);
        }
    }
}

// ---------------------------------------------------------------------------
// fp16 2-term GEMM: C = Ah*(Bh+Bl), A fp16-hi only. 4-stage ring, 2 CTAs/SM.
//   MODE 0: +bias -> bf16 hi/lo pair out (Q-proj)
//   MODE 4: +bias -> fp32 out (O-proj)
// ---------------------------------------------------------------------------
template<int MODE>
__global__ void __launch_bounds__(256, 2)
mma_gemm_f16(const __half* __restrict__ Ah, const __half* __restrict__ Bh,
             const __half* __restrict__ Bl, const float* __restrict__ bias,
             float* __restrict__ Cf, __nv_bfloat16* __restrict__ Ch,
             __nv_bfloat16* __restrict__ Cl, int K, int lda, int ldb, int ldc)
{
    __shared__ __align__(16) char smem[SMEM_BYTES];
    const int tid = threadIdx.x;
    const int wid = tid >> 5;
    const int lane = tid & 31;
    const int g = lane >> 2, ti = lane & 3;
    const int mwb = (wid >> 2) * 64;
    const int nwb = (wid & 3) * 32;
    const uint32_t sbase = smem_to_u32(smem);

    const int m0 = blockIdx.y * 128;
    const int n0 = blockIdx.x * 128;

    const int crow = tid >> 1;
    const int cseg = tid & 1;
    const size_t asrc = (size_t)(m0 + crow) * lda + cseg * 8;
    const size_t bsrc = (size_t)(n0 + crow) * ldb + cseg * 8;
    const uint32_t cdst = swz(crow, cseg);

    const int nchunk = K / BK;

    auto issue = [&](int c) {
        const uint32_t st = sbase + (c & 3) * FSTG;
        const int kt = c * BK;
        cp16(st + cdst,          Ah + asrc + kt);
        cp16(st + cdst + FT,     Bh + bsrc + kt);
        cp16(st + cdst + 2*FT,   Bl + bsrc + kt);
    };

    float acc[4][4][4];
#pragma unroll
    for (int i = 0; i < 4; i++)
#pragma unroll
        for (int j = 0; j < 4; j++)
#pragma unroll
            for (int q = 0; q < 4; q++) acc[i][j][q] = 0.f;

    issue(0); CP_COMMIT();
    issue(1); CP_COMMIT();
    issue(2); CP_COMMIT();

    const int arow = lane & 15;
    const int aseg = lane >> 4;
    const int brow = (lane & 7) + ((lane >> 4) << 3);
    const int bseg = (lane >> 3) & 1;

    for (int c = 0; c < nchunk; c++) {
        CP_WAIT2();
        __syncthreads();
        if (c + 3 < nchunk) issue(c + 3);
        CP_COMMIT();

        const uint32_t sbuf = sbase + (c & 3) * FSTG;
        uint32_t ah[4][4];
#pragma unroll
        for (int mf = 0; mf < 4; mf++)
            ldmx4(ah[mf], sbuf + swz(mwb + mf * 16 + arow, aseg));
#pragma unroll
        for (int np = 0; np < 2; np++) {
            uint32_t rh[4], rl[4];
            uint32_t bd = sbuf + FT + swz(nwb + np * 16 + brow, bseg);
            ldmx4(rh, bd);
            ldmx4(rl, bd + FT);
#pragma unroll
            for (int mf = 0; mf < 4; mf++) {
                mma16816h(acc[mf][2*np],   ah[mf], rh);
                mma16816h(acc[mf][2*np+1], ah[mf], rh + 2);
                mma16816h(acc[mf][2*np],   ah[mf], rl);
                mma16816h(acc[mf][2*np+1], ah[mf], rl + 2);
            }
        }
    }
    __syncthreads();

    float* stage = (float*)smem;
#pragma unroll
    for (int p = 0; p < 2; p++) {
        if (p) __syncthreads();
#pragma unroll
        for (int mf = 0; mf < 4; mf++)
#pragma unroll
            for (int e = 0; e < 2; e++) {
                const int nf = 2 * p + e;
                const int row = mwb + mf * 16 + g;
                const int cm = (wid & 3) * 16 + e * 8 + ti * 2;
                *(float2*)&stage[row * STAGE_PITCH + cm] =
                    make_float2(acc[mf][nf][0], acc[mf][nf][1]);
                *(float2*)&stage[(row + 8) * STAGE_PITCH + cm] =
                    make_float2(acc[mf][nf][2], acc[mf][nf][3]);
            }
        __syncthreads();
#pragma unroll
        for (int it = 0; it < 8; it++) {
            const int lin = it * 1024 + tid * 4;
            const int row = lin >> 6;
            const int cm = lin & 63;
            const int col = ((cm >> 4) << 5) + (p << 4) + (cm & 15);
            float4 v = *(float4*)&stage[row * STAGE_PITCH + cm];
            float4 b4 = *(const float4*)(bias + n0 + col);
            if (MODE == 0) {
                uint32_t h0, l0, h1, l1;
                split_pair(v.x + b4.x, v.y + b4.y, h0, l0);
                split_pair(v.z + b4.z, v.w + b4.w, h1, l1);
                size_t off = (size_t)(m0 + row) * ldc + n0 + col;
                *(uint2*)(Ch + off) = make_uint2(h0, h1);
                *(uint2*)(Cl + off) = make_uint2(l0, l1);
            } else {
                float4 o = make_float4(v.x + b4.x, v.y + b4.y, v.z + b4.z, v.w + b4.w);
                *(float4*)(Cf + (size_t)(m0 + row) * ldc + n0 + col) = o;
            }
        }
    }
}

// ---------------------------------------------------------------------------
// Fused attention: scores + softmax + PV (bf16 3-term), ctx -> single fp16
// ---------------------------------------------------------------------------
__global__ void __launch_bounds__(256, 1)
fused_attn_kernel(const __nv_bfloat16* __restrict__ Qh, const __nv_bfloat16* __restrict__ Ql,
                  const __nv_bfloat16* __restrict__ Kh, const __nv_bfloat16* __restrict__ Kl,
                  const __nv_bfloat16* __restrict__ Vth, const __nv_bfloat16* __restrict__ Vtl,
                  const int* __restrict__ mask, __half* __restrict__ C16)
{
    extern __shared__ __align__(16) char dsm[];
    __shared__ float red[128][4];
    __shared__ int smask[T_DIM];

    const int tid = threadIdx.x;
    const int wid = tid >> 5;
    const int lane = tid & 31;
    const int g = lane >> 2, ti = lane & 3;
    const int mwb = (wid >> 2) * 64;
    const int nwb = (wid & 3) * 64;
    const uint32_t sbase = smem_to_u32(dsm);

    const int m0 = blockIdx.y * 128;
    const int z = blockIdx.z;
    const int bb = z >> 4, hh = z & 15;
    const __nv_bfloat16* pQh = Qh + (size_t)bb * S_DIM * H_DIM + hh * HD_DIM;
    const __nv_bfloat16* pQl = Ql + (size_t)bb * S_DIM * H_DIM + hh * HD_DIM;
    const __nv_bfloat16* pKh = Kh + (size_t)bb * T_DIM * H_DIM + hh * HD_DIM;
    const __nv_bfloat16* pKl = Kl + (size_t)bb * T_DIM * H_DIM + hh * HD_DIM;

    smask[tid] = mask[bb * T_DIM + tid];

    const int crow = tid >> 1, cseg = tid & 1;
    const size_t qsrc  = (size_t)(m0 + crow) * H_DIM + cseg * 8;
    const size_t ksrc0 = (size_t)crow * H_DIM + cseg * 8;
    const size_t ksrc1 = (size_t)(crow + 128) * H_DIM + cseg * 8;
    const uint32_t adst = swz(crow, cseg);
    const uint32_t bdst0 = swz(crow, cseg);
    const uint32_t bdst1 = swz(crow + 128, cseg);

    auto issue = [&](int c) {
        const uint32_t st = sbase + (c % 3) * SS_STAGE;
        const int kt = c * BK;
        cp16(st + adst,                       pQh + qsrc + kt);
        cp16(st + adst + SS_ATB,              pQl + qsrc + kt);
        cp16(st + 2*SS_ATB + bdst0,           pKh + ksrc0 + kt);
        cp16(st + 2*SS_ATB + bdst1,           pKh + ksrc1 + kt);
        cp16(st + 2*SS_ATB + SS_BTB + bdst0,  pKl + ksrc0 + kt);
        cp16(st + 2*SS_ATB + SS_BTB + bdst1,  pKl + ksrc1 + kt);
    };

    float acc[4][8][4];
#pragma unroll
    for (int i = 0; i < 4; i++)
#pragma unroll
        for (int j = 0; j < 8; j++)
#pragma unroll
            for (int q = 0; q < 4; q++) acc[i][j][q] = 0.f;

    issue(0); CP_COMMIT();
    issue(1); CP_COMMIT();

    const int arow = lane & 15;
    const int aseg = lane >> 4;
    const int brow = (lane & 7) + ((lane >> 4) << 3);
    const int bseg = (lane >> 3) & 1;

    for (int c = 0; c < 8; c++) {
        CP_WAIT1();
        __syncthreads();
        if (c + 2 < 8) issue(c + 2);
        CP_COMMIT();

        const uint32_t sbuf = sbase + (c % 3) * SS_STAGE;
        uint32_t ah[4][4], al[4][4];
#pragma unroll
        for (int mf = 0; mf < 4; mf++) {
            uint32_t ad = sbuf + swz(mwb + mf * 16 + arow, aseg);
            ldmx4(ah[mf], ad);
            ldmx4(al[mf], ad + SS_ATB);
        }
#pragma unroll
        for (int np = 0; np < 4; np++) {
            uint32_t rh[4], rl[4];
            uint32_t bd = sbuf + 2*SS_ATB + swz(nwb + np * 16 + brow, bseg);
            ldmx4(rh, bd);
            ldmx4(rl, bd + SS_BTB);
#pragma unroll
            for (int mf = 0; mf < 4; mf++) {
                mma16816(acc[mf][2*np],   ah[mf], rh);
                mma16816(acc[mf][2*np+1], ah[mf], rh + 2);
                mma16816(acc[mf][2*np],   ah[mf], rl);
                mma16816(acc[mf][2*np+1], ah[mf], rl + 2);
                mma16816(acc[mf][2*np],   al[mf], rh);
                mma16816(acc[mf][2*np+1], al[mf], rh + 2);
            }
        }
    }
    __syncthreads();

    // softmax
    const float invs = 0.08838834764831845f;
    float rmax[4][2], rsum[4][2];
#pragma unroll
    for (int mf = 0; mf < 4; mf++) {
        float mx0 = -1e30f, mx1 = -1e30f;
#pragma unroll
        for (int nf = 0; nf < 8; nf++) {
            const int col = nwb + nf * 8 + ti * 2;
            const bool k0 = smask[col] != 0;
            const bool k1 = smask[col + 1] != 0;
            float* a = acc[mf][nf];
            a[0] = k0 ? fminf(fmaxf(a[0] * invs, -50.f), 50.f) : -50.f;
            a[1] = k1 ? fminf(fmaxf(a[1] * invs, -50.f), 50.f) : -50.f;
            a[2] = k0 ? fminf(fmaxf(a[2] * invs, -50.f), 50.f) : -50.f;
            a[3] = k1 ? fminf(fmaxf(a[3] * invs, -50.f), 50.f) : -50.f;
            mx0 = fmaxf(mx0, fmaxf(a[0], a[1]));
            mx1 = fmaxf(mx1, fmaxf(a[2], a[3]));
        }
        mx0 = fmaxf(mx0, __shfl_xor_sync(0xffffffffu, mx0, 1));
        mx0 = fmaxf(mx0, __shfl_xor_sync(0xffffffffu, mx0, 2));
        mx1 = fmaxf(mx1, __shfl_xor_sync(0xffffffffu, mx1, 1));
        mx1 = fmaxf(mx1, __shfl_xor_sync(0xffffffffu, mx1, 2));
        if (ti == 0) {
            red[mwb + mf * 16 + g][wid & 3]     = mx0;
            red[mwb + mf * 16 + g + 8][wid & 3] = mx1;
        }
    }
    __syncthreads();
#pragma unroll
    for (int mf = 0; mf < 4; mf++) {
        float4 r0 = *(float4*)red[mwb + mf * 16 + g];
        rmax[mf][0] = fmaxf(fmaxf(r0.x, r0.y), fmaxf(r0.z, r0.w));
        float4 r1 = *(float4*)red[mwb + mf * 16 + g + 8];
        rmax[mf][1] = fmaxf(fmaxf(r1.x, r1.y), fmaxf(r1.z, r1.w));
    }
    __syncthreads();
#pragma unroll
    for (int mf = 0; mf < 4; mf++) {
        float s0 = 0.f, s1 = 0.f;
#pragma unroll
        for (int nf = 0; nf < 8; nf++) {
            float* a = acc[mf][nf];
            a[0] = __expf(a[0] - rmax[mf][0]); s0 += a[0];
            a[1] = __expf(a[1] - rmax[mf][0]); s0 += a[1];
            a[2] = __expf(a[2] - rmax[mf][1]); s1 += a[2];
            a[3] = __expf(a[3] - rmax[mf][1]); s1 += a[3];
        }
        s0 += __shfl_xor_sync(0xffffffffu, s0, 1);
        s0 += __shfl_xor_sync(0xffffffffu, s0, 2);
        s1 += __shfl_xor_sync(0xffffffffu, s1, 1);
        s1 += __shfl_xor_sync(0xffffffffu, s1, 2);
        if (ti == 0) {
            red[mwb + mf * 16 + g][wid & 3]     = s0;
            red[mwb + mf * 16 + g + 8][wid & 3] = s1;
        }
    }
    __syncthreads();
#pragma unroll
    for (int mf = 0; mf < 4; mf++) {
        float4 r0 = *(float4*)red[mwb + mf * 16 + g];
        rsum[mf][0] = 1.f / (r0.x + r0.y + r0.z + r0.w);
        float4 r1 = *(float4*)red[mwb + mf * 16 + g + 8];
        rsum[mf][1] = 1.f / (r1.x + r1.y + r1.z + r1.w);
    }

    // stage P hi/lo into SMEM A-operand tiles
#pragma unroll
    for (int mf = 0; mf < 4; mf++) {
        const int r0 = mwb + mf * 16 + g;
#pragma unroll
        for (int nf = 0; nf < 8; nf++) {
            const int col = nwb + nf * 8 + ti * 2;
            const int ch = col >> 4;
            const int colc = col & 15;
            const uint32_t cb = ch * 8192 + (((colc >> 3) << 4) ^ ((r0 & 4) << 2))
                              + (colc & 7) * 2 + r0 * 32;
            float* a = acc[mf][nf];
            uint32_t h0, l0, h1, l1;
            split_pair(a[0] * rsum[mf][0], a[1] * rsum[mf][0], h0, l0);
            split_pair(a[2] * rsum[mf][1], a[3] * rsum[mf][1], h1, l1);
            *(uint32_t*)(dsm + cb)               = h0;
            *(uint32_t*)(dsm + cb + 4096)        = l0;
            *(uint32_t*)(dsm + cb + 256)         = h1;
            *(uint32_t*)(dsm + cb + 256 + 4096)  = l1;
        }
    }
    __syncthreads();

    // PV mainloop
    const __nv_bfloat16* pVh = Vth + (size_t)z * HD_DIM * T_DIM;
    const __nv_bfloat16* pVl = Vtl + (size_t)z * HD_DIM * T_DIM;
    const size_t vsrc = (size_t)crow * T_DIM + cseg * 8;
    const uint32_t vdst = swz(crow, cseg);
    auto issueV = [&](int c) {
        const uint32_t st = sbase + VOFF + (c % 3) * 8192;
        cp16(st + vdst,        pVh + vsrc + c * 16);
        cp16(st + vdst + 4096, pVl + vsrc + c * 16);
    };

    float ctx[4][4][4];
#pragma unroll
    for (int i = 0; i < 4; i++)
#pragma unroll
        for (int j = 0; j < 4; j++)
#pragma unroll
            for (int q = 0; q < 4; q++) ctx[i][j][q] = 0.f;

    issueV(0); CP_COMMIT();
    issueV(1); CP_COMMIT();

    const int nwb2 = (wid & 3) * 32;
    for (int c = 0; c < 16; c++) {
        CP_WAIT1();
        __syncthreads();
        if (c + 2 < 16) issueV(c + 2);
        CP_COMMIT();

        const uint32_t pbuf = sbase + c * 8192;
        const uint32_t vbuf = sbase + VOFF + (c % 3) * 8192;
        uint32_t ah[4][4], al[4][4];
#pragma unroll
        for (int mf = 0; mf < 4; mf++) {
            uint32_t ad = pbuf + swz(mwb + mf * 16 + arow, aseg);
            ldmx4(ah[mf], ad);
            ldmx4(al[mf], ad + 4096);
        }
#pragma unroll
        for (int np = 0; np < 2; np++) {
            uint32_t rh[4], rl[4];
            uint32_t bd = vbuf + swz(nwb2 + np * 16 + brow, bseg);
            ldmx4(rh, bd);
            ldmx4(rl, bd + 4096);
#pragma unroll
            for (int mf = 0; mf < 4; mf++) {
                mma16816(ctx[mf][2*np],   ah[mf], rh);
                mma16816(ctx[mf][2*np+1], ah[mf], rh + 2);
                mma16816(ctx[mf][2*np],   ah[mf], rl);
                mma16816(ctx[mf][2*np+1], ah[mf], rl + 2);
                mma16816(ctx[mf][2*np],   al[mf], rh);
                mma16816(ctx[mf][2*np+1], al[mf], rh + 2);
            }
        }
    }
    __syncthreads();

    // ctx scatter epilogue -> single fp16
    float* stage = (float*)dsm;
#pragma unroll
    for (int p = 0; p < 2; p++) {
        if (p) __syncthreads();
#pragma unroll
        for (int mf = 0; mf < 4; mf++)
#pragma unroll
            for (int e = 0; e < 2; e++) {
                const int nf = 2 * p + e;
                const int row = mwb + mf * 16 + g;
                const int cm = (wid & 3) * 16 + e * 8 + ti * 2;
                *(float2*)&stage[row * STAGE_PITCH + cm] =
                    make_float2(ctx[mf][nf][0], ctx[mf][nf][1]);
                *(float2*)&stage[(row + 8) * STAGE_PITCH + cm] =
                    make_float2(ctx[mf][nf][2], ctx[mf][nf][3]);
            }
        __syncthreads();
#pragma unroll
        for (int it = 0; it < 8; it++) {
            const int lin = it * 1024 + tid * 4;
            const int row = lin >> 6;
            const int cm = lin & 63;
            const int col = ((cm >> 4) << 5) + (p << 4) + (cm & 15);
            float4 v = *(float4*)&stage[row * STAGE_PITCH + cm];
            __half2 a = __floats2half2_rn(v.x, v.y);
            __half2 b = __floats2half2_rn(v.z, v.w);
            size_t off = (size_t)(bb * S_DIM + m0 + row) * H_DIM + hh * HD_DIM + col;
            *(uint2*)(C16 + off) = make_uint2(*(uint32_t*)&a, *(uint32_t*)&b);
        }
    }
}

// ---------------------------------------------------------------------------
// LayerNorm
// ---------------------------------------------------------------------------
__device__ __forceinline__ float block_sum(float v)
{
    __shared__ float red[8];
#pragma unroll
    for (int o = 16; o; o >>= 1) v += __shfl_xor_sync(0xffffffffu, v, o);
    int w = threadIdx.x >> 5;
    if ((threadIdx.x & 31) == 0) red[w] = v;
    __syncthreads();
    float t = (threadIdx.x < 8) ? red[threadIdx.x] : 0.f;
    if (threadIdx.x < 32) {
#pragma unroll
        for (int o = 4; o; o >>= 1) t += __shfl_xor_sync(0xffffffffu, t, o);
        if (threadIdx.x == 0) red[0] = t;
    }
    __syncthreads();
    float r = red[0];
    __syncthreads();
    return r;
}

__global__ void ln_kernel(const float* __restrict__ D, const float* __restrict__ gamma,
                          const float* __restrict__ beta, const float* __restrict__ rsp,
                          float* __restrict__ out)
{
    int row = blockIdx.x;
    int tid = threadIdx.x;
    float rs = fminf(fmaxf(rsp[0], 0.f), 0.3f);

    const float* d = D + (size_t)row * H_DIM;
    float4 u0 = *(const float4*)(d + tid * 4);
    float4 u1 = *(const float4*)(d + 1024 + tid * 4);
    float x[8] = {rs*u0.x, rs*u0.y, rs*u0.z, rs*u0.w,
                  rs*u1.x, rs*u1.y, rs*u1.z, rs*u1.w};

    float ps = 0.f;
#pragma unroll
    for (int i = 0; i < 8; i++) ps += x[i];
    float mean = block_sum(ps) * (1.f / 2048.f);

    float pv = 0.f;
#pragma unroll
    for (int i = 0; i < 8; i++) { float dd = x[i] - mean; pv += dd * dd; }
    float var = block_sum(pv) * (1.f / 2048.f);
    float inv = rsqrtf(var + 1e-5f);

    float4 gz0 = *(const float4*)(gamma + tid * 4);
    float4 gz1 = *(const float4*)(gamma + 1024 + tid * 4);
    float4 bz0 = *(const float4*)(beta + tid * 4);
    float4 bz1 = *(const float4*)(beta + 1024 + tid * 4);

    float* o = out + (size_t)row * H_DIM;
    *(float4*)(o + tid * 4) = make_float4(
        (x[0]-mean)*inv*gz0.x + bz0.x, (x[1]-mean)*inv*gz0.y + bz0.y,
        (x[2]-mean)*inv*gz0.z + bz0.z, (x[3]-mean)*inv*gz0.w + bz0.w);
    *(float4*)(o + 1024 + tid * 4) = make_float4(
        (x[4]-mean)*inv*gz1.x + bz1.x, (x[5]-mean)*inv*gz1.y + bz1.y,
        (x[6]-mean)*inv*gz1.z + bz1.z, (x[7]-mean)*inv*gz1.w + bz1.w);
}

// ---------------------------------------------------------------------------
// Launch
// ---------------------------------------------------------------------------
extern "C" void kernel_launch(void* const* d_in, const int* in_sizes, int n_in,
                              void* d_out, int out_size)
{
    const float* hs    = (const float*)d_in[0];
    const float* at    = (const float*)d_in[1];
    const int*   mask  = (const int*)  d_in[2];
    const float* Wq    = (const float*)d_in[3];
    const float* bq    = (const float*)d_in[4];
    const float* Wk    = (const float*)d_in[5];
    const float* bk    = (const float*)d_in[6];
    const float* Wv    = (const float*)d_in[7];
    const float* bv    = (const float*)d_in[8];
    const float* Wo    = (const float*)d_in[9];
    const float* bo    = (const float*)d_in[10];
    const float* gamma = (const float*)d_in[11];
    const float* beta  = (const float*)d_in[12];
    const float* rsp   = (const float*)d_in[13];
    float* out = (float*)d_out;

    __half *hs16, *Wq16h, *Wq16l, *Wo16h, *Wo16l, *C16;
    __nv_bfloat16 *ath, *atl, *Wkh, *Wkl, *Wvh, *Wvl;
    __nv_bfloat16 *Qh, *Ql, *Kh, *Kl, *Vth, *Vtl;
    float *Db;
    cudaGetSymbolAddress((void**)&hs16,  g_hs16);
    cudaGetSymbolAddress((void**)&Wq16h, g_Wq16h); cudaGetSymbolAddress((void**)&Wq16l, g_Wq16l);
    cudaGetSymbolAddress((void**)&Wo16h, g_Wo16h); cudaGetSymbolAddress((void**)&Wo16l, g_Wo16l);
    cudaGetSymbolAddress((void**)&C16,   g_C16);
    cudaGetSymbolAddress((void**)&ath, g_ath); cudaGetSymbolAddress((void**)&atl, g_atl);
    cudaGetSymbolAddress((void**)&Wkh, g_Wkh); cudaGetSymbolAddress((void**)&Wkl, g_Wkl);
    cudaGetSymbolAddress((void**)&Wvh, g_Wvh); cudaGetSymbolAddress((void**)&Wvl, g_Wvl);
    cudaGetSymbolAddress((void**)&Qh,  g_Qh);  cudaGetSymbolAddress((void**)&Ql,  g_Ql);
    cudaGetSymbolAddress((void**)&Kh,  g_Kh);  cudaGetSymbolAddress((void**)&Kl,  g_Kl);
    cudaGetSymbolAddress((void**)&Vth, g_Vth); cudaGetSymbolAddress((void**)&Vtl, g_Vtl);
    cudaGetSymbolAddress((void**)&Db,  g_D);

    cudaFuncSetAttribute(fused_attn_kernel,
                         cudaFuncAttributeMaxDynamicSharedMemorySize, SS_SMEM);

    // Pre-pass: fp16 cast/split for Q/O path, bf16 splits for K/V/attention path
    cast16_kernel<<<16384, 256>>>(hs, hs16);
    split16_kernel<<<4096, 256>>>(Wq, Wq16h, Wq16l);
    split16_kernel<<<4096, 256>>>(Wo, Wo16h, Wo16l);
    split_kernel<<<2048, 256>>>(at, ath, atl);
    split_kernel<<<4096, 256>>>(Wk, Wkh, Wkl);
    split_kernel<<<4096, 256>>>(Wv, Wvh, Wvl);

    // Q projection (fp16 2-term) -> Qh/Ql bf16 pair
    mma_gemm_f16<0><<<dim3(16, 64), 256>>>(hs16, Wq16h, Wq16l, bq,
                                           nullptr, Qh, Ql, 2048, 2048, 2048, 2048);
    // K projection (bf16 3-term) -> Kh/Kl
    mma_gemm<0><<<dim3(16, 8), 256>>>(ath, atl, Wkh, Wkl, bk,
                                      Kh, Kl, 2048, 2048, 2048, 2048);
    // V projection (bf16 3-term, A=Wv, B=at) -> Vt hi/lo [b,h,d,t]
    mma_gemm<1><<<dim3(8, 16), 256>>>(Wvh, Wvl, ath, atl, bv,
                                      Vth, Vtl, 2048, 2048, 2048, 0);
    // Fused scores + softmax + PV -> ctx fp16
    fused_attn_kernel<<<dim3(1, 16, 64), 256, SS_SMEM>>>(Qh, Ql, Kh, Kl, Vth, Vtl,
                                                         mask, C16);
    // O projection (fp16 2-term) -> fp32 D
    mma_gemm_f16<4><<<dim3(16, 64), 256>>>(C16, Wo16h, Wo16l, bo,
                                           Db, nullptr, nullptr, 2048, 2048, 2048, 2048);
    // residual scale + LayerNorm
    ln_kernel<<<8192, 256>>>(Db, gamma, beta, rsp, out);
}

// round 12
// speedup vs baseline: 2.0422x; 1.1143x over previous
#include <cuda_runtime.h>
#include <cuda_fp16.h>
#include <cstdint>
#include <math.h>

#define B_DIM 4
#define S_DIM 2048
#define T_DIM 256
#define H_DIM 2048
#define NHEAD 16
#define HD_DIM 128

#define BK 16
#define STAGE_PITCH 68       // fp32 epilogue staging pitch

// fp16 2-term GEMM: 128x128 tile, BK=16, 4-stage ring (12KB/stage), 2 CTAs/SM
#define FT 4096
#define FSTG 12288
#define SMEM_BYTES 49152

// Fused attention (all fp16 2-term)
#define AS_KH 4096           // K-hi tile offset in scores stage (Q at 0)
#define AS_KL 12288
#define AS_STG 20480         // stage = Q 4K + Kh 8K + Kl 8K
#define AS_VOFF 65536        // V ring after 16x4KB P tiles
#define AS_SMEM (AS_VOFF + 3*8192)   // 90112

// ---------------------------------------------------------------------------
// Persistent scratch
// ---------------------------------------------------------------------------
__device__ __half g_hs16[8192*2048];
__device__ __half g_at16h[1024*2048], g_at16l[1024*2048];
__device__ __half g_Wq16h[2048*2048], g_Wq16l[2048*2048];
__device__ __half g_Wk16h[2048*2048], g_Wk16l[2048*2048];
__device__ __half g_Wv16[2048*2048];
__device__ __half g_Wo16h[2048*2048], g_Wo16l[2048*2048];
__device__ __half g_Q16[8192*2048];
__device__ __half g_K16h[1024*2048], g_K16l[1024*2048];
__device__ __half g_Vt16h[64*128*256], g_Vt16l[64*128*256];
__device__ __half g_C16[8192*2048];
__device__ float  g_D[8192*2048];

// ---------------------------------------------------------------------------
// Helpers
// ---------------------------------------------------------------------------
__device__ __forceinline__ uint32_t smem_to_u32(const void* p) {
    uint32_t a;
    asm("{ .reg .u64 t; cvta.to.shared.u64 t, %1; cvt.u32.u64 %0, t; }" : "=r"(a) : "l"(p));
    return a;
}
__device__ __forceinline__ void cp16(uint32_t dst, const void* src) {
    asm volatile("cp.async.cg.shared.global [%0], [%1], 16;" :: "r"(dst), "l"(src));
}
#define CP_COMMIT() asm volatile("cp.async.commit_group;")
#define CP_WAIT1()  asm volatile("cp.async.wait_group 1;")
#define CP_WAIT2()  asm volatile("cp.async.wait_group 2;")

__device__ __forceinline__ void ldmx4(uint32_t* r, uint32_t addr) {
    asm volatile("ldmatrix.sync.aligned.m8n8.x4.shared.b16 {%0,%1,%2,%3}, [%4];"
                 : "=r"(r[0]), "=r"(r[1]), "=r"(r[2]), "=r"(r[3]) : "r"(addr));
}
__device__ __forceinline__ void mma16816h(float* c, const uint32_t* a, const uint32_t* b) {
    asm volatile("mma.sync.aligned.m16n8k16.row.col.f32.f16.f16.f32 "
                 "{%0,%1,%2,%3}, {%4,%5,%6,%7}, {%8,%9}, {%0,%1,%2,%3};"
                 : "+f"(c[0]), "+f"(c[1]), "+f"(c[2]), "+f"(c[3])
                 : "r"(a[0]), "r"(a[1]), "r"(a[2]), "r"(a[3]), "r"(b[0]), "r"(b[1]));
}
__device__ __forceinline__ void split_pair_f16(float x0, float x1, uint32_t& hi, uint32_t& lo) {
    __half2 h = __floats2half2_rn(x0, x1);
    float r0 = x0 - __half2float(__low2half(h));
    float r1 = x1 - __half2float(__high2half(h));
    __half2 l = __floats2half2_rn(r0, r1);
    hi = *(uint32_t*)&h;
    lo = *(uint32_t*)&l;
}
__device__ __forceinline__ uint32_t pack_h2(float x0, float x1) {
    __half2 h = __floats2half2_rn(x0, x1);
    return *(uint32_t*)&h;
}
__device__ __forceinline__ uint32_t swz(int row, int seg) {
    return (row >> 7) * 4096 + (row & 127) * 32 + ((seg << 4) ^ ((row & 4) << 2));
}

// ---------------------------------------------------------------------------
// Pre-pass kernels
// ---------------------------------------------------------------------------
__global__ void split16_kernel(const float* __restrict__ in,
                               __half* __restrict__ hi, __half* __restrict__ lo)
{
    int idx = blockIdx.x * blockDim.x + threadIdx.x;
    float4 v = ((const float4*)in)[idx];
    uint32_t h0, l0, h1, l1;
    split_pair_f16(v.x, v.y, h0, l0);
    split_pair_f16(v.z, v.w, h1, l1);
    ((uint2*)hi)[idx] = make_uint2(h0, h1);
    ((uint2*)lo)[idx] = make_uint2(l0, l1);
}
__global__ void cast16_kernel(const float* __restrict__ in, __half* __restrict__ out)
{
    int idx = blockIdx.x * blockDim.x + threadIdx.x;
    float4 v = ((const float4*)in)[idx];
    ((uint2*)out)[idx] = make_uint2(pack_h2(v.x, v.y), pack_h2(v.z, v.w));
}

// ---------------------------------------------------------------------------
// fp16 2-term GEMM: C = Ah*(Bh+Bl). 4-stage ring, 2 CTAs/SM.
//   MODE 0: +bias[col] -> fp16 single (Q-proj)
//   MODE 1: +bias[col] -> fp16 hi/lo pair (K-proj)
//   MODE 2: +bias[row] -> fp16 hi/lo Vt scatter (V-proj, A=Wv B=at)
//   MODE 4: +bias[col] -> fp32 (O-proj)
// ---------------------------------------------------------------------------
template<int MODE>
__global__ void __launch_bounds__(256, 2)
mma_gemm_f16(const __half* __restrict__ Ah, const __half* __restrict__ Bh,
             const __half* __restrict__ Bl, const float* __restrict__ bias,
             float* __restrict__ Cf, __half* __restrict__ C1,
             __half* __restrict__ Ch, __half* __restrict__ Cl,
             int K, int lda, int ldb, int ldc)
{
    __shared__ __align__(16) char smem[SMEM_BYTES];
    const int tid = threadIdx.x;
    const int wid = tid >> 5;
    const int lane = tid & 31;
    const int g = lane >> 2, ti = lane & 3;
    const int mwb = (wid >> 2) * 64;
    const int nwb = (wid & 3) * 32;
    const uint32_t sbase = smem_to_u32(smem);

    const int m0 = blockIdx.y * 128;
    const int n0 = blockIdx.x * 128;

    const int crow = tid >> 1;
    const int cseg = tid & 1;
    const size_t asrc = (size_t)(m0 + crow) * lda + cseg * 8;
    const size_t bsrc = (size_t)(n0 + crow) * ldb + cseg * 8;
    const uint32_t cdst = swz(crow, cseg);

    const int nchunk = K / BK;

    auto issue = [&](int c) {
        const uint32_t st = sbase + (c & 3) * FSTG;
        const int kt = c * BK;
        cp16(st + cdst,          Ah + asrc + kt);
        cp16(st + cdst + FT,     Bh + bsrc + kt);
        cp16(st + cdst + 2*FT,   Bl + bsrc + kt);
    };

    float acc[4][4][4];
#pragma unroll
    for (int i = 0; i < 4; i++)
#pragma unroll
        for (int j = 0; j < 4; j++)
#pragma unroll
            for (int q = 0; q < 4; q++) acc[i][j][q] = 0.f;

    issue(0); CP_COMMIT();
    issue(1); CP_COMMIT();
    issue(2); CP_COMMIT();

    const int arow = lane & 15;
    const int aseg = lane >> 4;
    const int brow = (lane & 7) + ((lane >> 4) << 3);
    const int bseg = (lane >> 3) & 1;

    for (int c = 0; c < nchunk; c++) {
        CP_WAIT2();
        __syncthreads();
        if (c + 3 < nchunk) issue(c + 3);
        CP_COMMIT();

        const uint32_t sbuf = sbase + (c & 3) * FSTG;
        uint32_t ah[4][4];
#pragma unroll
        for (int mf = 0; mf < 4; mf++)
            ldmx4(ah[mf], sbuf + swz(mwb + mf * 16 + arow, aseg));
#pragma unroll
        for (int np = 0; np < 2; np++) {
            uint32_t rh[4], rl[4];
            uint32_t bd = sbuf + FT + swz(nwb + np * 16 + brow, bseg);
            ldmx4(rh, bd);
            ldmx4(rl, bd + FT);
#pragma unroll
            for (int mf = 0; mf < 4; mf++) {
                mma16816h(acc[mf][2*np],   ah[mf], rh);
                mma16816h(acc[mf][2*np+1], ah[mf], rh + 2);
                mma16816h(acc[mf][2*np],   ah[mf], rl);
                mma16816h(acc[mf][2*np+1], ah[mf], rl + 2);
            }
        }
    }
    __syncthreads();

    float* stage = (float*)smem;
#pragma unroll
    for (int p = 0; p < 2; p++) {
        if (p) __syncthreads();
#pragma unroll
        for (int mf = 0; mf < 4; mf++)
#pragma unroll
            for (int e = 0; e < 2; e++) {
                const int nf = 2 * p + e;
                const int row = mwb + mf * 16 + g;
                const int cm = (wid & 3) * 16 + e * 8 + ti * 2;
                *(float2*)&stage[row * STAGE_PITCH + cm] =
                    make_float2(acc[mf][nf][0], acc[mf][nf][1]);
                *(float2*)&stage[(row + 8) * STAGE_PITCH + cm] =
                    make_float2(acc[mf][nf][2], acc[mf][nf][3]);
            }
        __syncthreads();
#pragma unroll
        for (int it = 0; it < 8; it++) {
            const int lin = it * 1024 + tid * 4;
            const int row = lin >> 6;
            const int cm = lin & 63;
            const int col = ((cm >> 4) << 5) + (p << 4) + (cm & 15);
            float4 v = *(float4*)&stage[row * STAGE_PITCH + cm];
            if (MODE == 0) {
                float4 b4 = *(const float4*)(bias + n0 + col);
                size_t off = (size_t)(m0 + row) * ldc + n0 + col;
                *(uint2*)(C1 + off) = make_uint2(pack_h2(v.x + b4.x, v.y + b4.y),
                                                 pack_h2(v.z + b4.z, v.w + b4.w));
            } else if (MODE == 1) {
                float4 b4 = *(const float4*)(bias + n0 + col);
                size_t off = (size_t)(m0 + row) * ldc + n0 + col;
                uint32_t h0, l0, h1, l1;
                split_pair_f16(v.x + b4.x, v.y + b4.y, h0, l0);
                split_pair_f16(v.z + b4.z, v.w + b4.w, h1, l1);
                *(uint2*)(Ch + off) = make_uint2(h0, h1);
                *(uint2*)(Cl + off) = make_uint2(l0, l1);
            } else if (MODE == 2) {
                const int gr = m0 + row;             // feature = h*128+d
                const int h = gr >> 7, d = gr & 127;
                const int n = n0 + col;              // b*256+t
                const int b = n >> 8, t = n & 255;
                const float br = bias[gr];
                size_t off = ((size_t)(b * NHEAD + h) * HD_DIM + d) * T_DIM + t;
                uint32_t h0, l0, h1, l1;
                split_pair_f16(v.x + br, v.y + br, h0, l0);
                split_pair_f16(v.z + br, v.w + br, h1, l1);
                *(uint2*)(Ch + off) = make_uint2(h0, h1);
                *(uint2*)(Cl + off) = make_uint2(l0, l1);
            } else {  // MODE 4
                float4 b4 = *(const float4*)(bias + n0 + col);
                float4 o = make_float4(v.x + b4.x, v.y + b4.y, v.z + b4.z, v.w + b4.w);
                *(float4*)(Cf + (size_t)(m0 + row) * ldc + n0 + col) = o;
            }
        }
    }
}

// ---------------------------------------------------------------------------
// Fused attention, all fp16 2-term:
//  scores = Q16 * (K16h + K16l); softmax; P -> single fp16 SMEM tiles;
//  ctx = P * (V16h + V16l); ctx -> single fp16 scatter
// ---------------------------------------------------------------------------
__global__ void __launch_bounds__(256, 1)
fused_attn_kernel(const __half* __restrict__ Q16,
                  const __half* __restrict__ K16h, const __half* __restrict__ K16l,
                  const __half* __restrict__ V16h, const __half* __restrict__ V16l,
                  const int* __restrict__ mask, __half* __restrict__ C16)
{
    extern __shared__ __align__(16) char dsm[];
    __shared__ float red[128][4];
    __shared__ int smask[T_DIM];

    const int tid = threadIdx.x;
    const int wid = tid >> 5;
    const int lane = tid & 31;
    const int g = lane >> 2, ti = lane & 3;
    const int mwb = (wid >> 2) * 64;
    const int nwb = (wid & 3) * 64;
    const uint32_t sbase = smem_to_u32(dsm);

    const int m0 = blockIdx.y * 128;
    const int z = blockIdx.z;
    const int bb = z >> 4, hh = z & 15;
    const __half* pQ  = Q16  + (size_t)bb * S_DIM * H_DIM + hh * HD_DIM;
    const __half* pKh = K16h + (size_t)bb * T_DIM * H_DIM + hh * HD_DIM;
    const __half* pKl = K16l + (size_t)bb * T_DIM * H_DIM + hh * HD_DIM;

    smask[tid] = mask[bb * T_DIM + tid];

    const int crow = tid >> 1, cseg = tid & 1;
    const size_t qsrc  = (size_t)(m0 + crow) * H_DIM + cseg * 8;
    const size_t ksrc0 = (size_t)crow * H_DIM + cseg * 8;
    const size_t ksrc1 = (size_t)(crow + 128) * H_DIM + cseg * 8;
    const uint32_t adst = swz(crow, cseg);
    const uint32_t bdst0 = swz(crow, cseg);
    const uint32_t bdst1 = swz(crow + 128, cseg);

    auto issue = [&](int c) {
        const uint32_t st = sbase + (c % 3) * AS_STG;
        const int kt = c * BK;
        cp16(st + adst,            pQ  + qsrc + kt);
        cp16(st + AS_KH + bdst0,   pKh + ksrc0 + kt);
        cp16(st + AS_KH + bdst1,   pKh + ksrc1 + kt);
        cp16(st + AS_KL + bdst0,   pKl + ksrc0 + kt);
        cp16(st + AS_KL + bdst1,   pKl + ksrc1 + kt);
    };

    float acc[4][8][4];
#pragma unroll
    for (int i = 0; i < 4; i++)
#pragma unroll
        for (int j = 0; j < 8; j++)
#pragma unroll
            for (int q = 0; q < 4; q++) acc[i][j][q] = 0.f;

    issue(0); CP_COMMIT();
    issue(1); CP_COMMIT();

    const int arow = lane & 15;
    const int aseg = lane >> 4;
    const int brow = (lane & 7) + ((lane >> 4) << 3);
    const int bseg = (lane >> 3) & 1;

    for (int c = 0; c < 8; c++) {          // K = HD = 128
        CP_WAIT1();
        __syncthreads();
        if (c + 2 < 8) issue(c + 2);
        CP_COMMIT();

        const uint32_t sbuf = sbase + (c % 3) * AS_STG;
        uint32_t ah[4][4];
#pragma unroll
        for (int mf = 0; mf < 4; mf++)
            ldmx4(ah[mf], sbuf + swz(mwb + mf * 16 + arow, aseg));
#pragma unroll
        for (int np = 0; np < 4; np++) {
            uint32_t rh[4], rl[4];
            uint32_t bd = sbuf + AS_KH + swz(nwb + np * 16 + brow, bseg);
            ldmx4(rh, bd);
            ldmx4(rl, bd + (AS_KL - AS_KH));
#pragma unroll
            for (int mf = 0; mf < 4; mf++) {
                mma16816h(acc[mf][2*np],   ah[mf], rh);
                mma16816h(acc[mf][2*np+1], ah[mf], rh + 2);
                mma16816h(acc[mf][2*np],   ah[mf], rl);
                mma16816h(acc[mf][2*np+1], ah[mf], rl + 2);
            }
        }
    }

    // Prefetch first V tiles (region does not overlap scores stages)
    const __half* pVh = V16h + (size_t)z * HD_DIM * T_DIM;
    const __half* pVl = V16l + (size_t)z * HD_DIM * T_DIM;
    const size_t vsrc = (size_t)crow * T_DIM + cseg * 8;
    const uint32_t vdst = swz(crow, cseg);
    auto issueV = [&](int c) {
        const uint32_t st = sbase + AS_VOFF + (c % 3) * 8192;
        cp16(st + vdst,        pVh + vsrc + c * 16);
        cp16(st + vdst + 4096, pVl + vsrc + c * 16);
    };
    issueV(0); CP_COMMIT();
    issueV(1); CP_COMMIT();
    __syncthreads();   // all warps done with scores stages before P overwrite

    // ---- mask/scale/clip + per-row softmax ----
    const float invs = 0.08838834764831845f;   // 1/sqrt(128)
    float rmax[4][2], rsum[4][2];
#pragma unroll
    for (int mf = 0; mf < 4; mf++) {
        float mx0 = -1e30f, mx1 = -1e30f;
#pragma unroll
        for (int nf = 0; nf < 8; nf++) {
            const int col = nwb + nf * 8 + ti * 2;
            const bool k0 = smask[col] != 0;
            const bool k1 = smask[col + 1] != 0;
            float* a = acc[mf][nf];
            a[0] = k0 ? fminf(fmaxf(a[0] * invs, -50.f), 50.f) : -50.f;
            a[1] = k1 ? fminf(fmaxf(a[1] * invs, -50.f), 50.f) : -50.f;
            a[2] = k0 ? fminf(fmaxf(a[2] * invs, -50.f), 50.f) : -50.f;
            a[3] = k1 ? fminf(fmaxf(a[3] * invs, -50.f), 50.f) : -50.f;
            mx0 = fmaxf(mx0, fmaxf(a[0], a[1]));
            mx1 = fmaxf(mx1, fmaxf(a[2], a[3]));
        }
        mx0 = fmaxf(mx0, __shfl_xor_sync(0xffffffffu, mx0, 1));
        mx0 = fmaxf(mx0, __shfl_xor_sync(0xffffffffu, mx0, 2));
        mx1 = fmaxf(mx1, __shfl_xor_sync(0xffffffffu, mx1, 1));
        mx1 = fmaxf(mx1, __shfl_xor_sync(0xffffffffu, mx1, 2));
        if (ti == 0) {
            red[mwb + mf * 16 + g][wid & 3]     = mx0;
            red[mwb + mf * 16 + g + 8][wid & 3] = mx1;
        }
    }
    __syncthreads();
#pragma unroll
    for (int mf = 0; mf < 4; mf++) {
        float4 r0 = *(float4*)red[mwb + mf * 16 + g];
        rmax[mf][0] = fmaxf(fmaxf(r0.x, r0.y), fmaxf(r0.z, r0.w));
        float4 r1 = *(float4*)red[mwb + mf * 16 + g + 8];
        rmax[mf][1] = fmaxf(fmaxf(r1.x, r1.y), fmaxf(r1.z, r1.w));
    }
    __syncthreads();
#pragma unroll
    for (int mf = 0; mf < 4; mf++) {
        float s0 = 0.f, s1 = 0.f;
#pragma unroll
        for (int nf = 0; nf < 8; nf++) {
            float* a = acc[mf][nf];
            a[0] = __expf(a[0] - rmax[mf][0]); s0 += a[0];
            a[1] = __expf(a[1] - rmax[mf][0]); s0 += a[1];
            a[2] = __expf(a[2] - rmax[mf][1]); s1 += a[2];
            a[3] = __expf(a[3] - rmax[mf][1]); s1 += a[3];
        }
        s0 += __shfl_xor_sync(0xffffffffu, s0, 1);
        s0 += __shfl_xor_sync(0xffffffffu, s0, 2);
        s1 += __shfl_xor_sync(0xffffffffu, s1, 1);
        s1 += __shfl_xor_sync(0xffffffffu, s1, 2);
        if (ti == 0) {
            red[mwb + mf * 16 + g][wid & 3]     = s0;
            red[mwb + mf * 16 + g + 8][wid & 3] = s1;
        }
    }
    __syncthreads();
#pragma unroll
    for (int mf = 0; mf < 4; mf++) {
        float4 r0 = *(float4*)red[mwb + mf * 16 + g];
        rsum[mf][0] = 1.f / (r0.x + r0.y + r0.z + r0.w);
        float4 r1 = *(float4*)red[mwb + mf * 16 + g + 8];
        rsum[mf][1] = 1.f / (r1.x + r1.y + r1.z + r1.w);
    }

    // ---- stage P (single fp16) into SMEM A-operand tiles: chunk ch at ch*4096 ----
#pragma unroll
    for (int mf = 0; mf < 4; mf++) {
        const int r0 = mwb + mf * 16 + g;
#pragma unroll
        for (int nf = 0; nf < 8; nf++) {
            const int col = nwb + nf * 8 + ti * 2;
            const int ch = col >> 4;
            const int colc = col & 15;
            const uint32_t cb = ch * 4096 + (((colc >> 3) << 4) ^ ((r0 & 4) << 2))
                              + (colc & 7) * 2 + r0 * 32;
            float* a = acc[mf][nf];
            *(uint32_t*)(dsm + cb)       = pack_h2(a[0] * rsum[mf][0], a[1] * rsum[mf][0]);
            *(uint32_t*)(dsm + cb + 256) = pack_h2(a[2] * rsum[mf][1], a[3] * rsum[mf][1]);
        }
    }
    __syncthreads();

    // ---- PV mainloop: ctx[128 s][128 d], K = T = 256, 16 chunks ----
    float ctx[4][4][4];
#pragma unroll
    for (int i = 0; i < 4; i++)
#pragma unroll
        for (int j = 0; j < 4; j++)
#pragma unroll
            for (int q = 0; q < 4; q++) ctx[i][j][q] = 0.f;

    const int nwb2 = (wid & 3) * 32;
    for (int c = 0; c < 16; c++) {
        CP_WAIT1();
        __syncthreads();
        if (c + 2 < 16) issueV(c + 2);
        CP_COMMIT();

        const uint32_t pbuf = sbase + c * 4096;
        const uint32_t vbuf = sbase + AS_VOFF + (c % 3) * 8192;
        uint32_t ah[4][4];
#pragma unroll
        for (int mf = 0; mf < 4; mf++)
            ldmx4(ah[mf], pbuf + swz(mwb + mf * 16 + arow, aseg));
#pragma unroll
        for (int np = 0; np < 2; np++) {
            uint32_t rh[4], rl[4];
            uint32_t bd = vbuf + swz(nwb2 + np * 16 + brow, bseg);
            ldmx4(rh, bd);
            ldmx4(rl, bd + 4096);
#pragma unroll
            for (int mf = 0; mf < 4; mf++) {
                mma16816h(ctx[mf][2*np],   ah[mf], rh);
                mma16816h(ctx[mf][2*np+1], ah[mf], rh + 2);
                mma16816h(ctx[mf][2*np],   ah[mf], rl);
                mma16816h(ctx[mf][2*np+1], ah[mf], rl + 2);
            }
        }
    }
    __syncthreads();

    // ---- ctx scatter -> single fp16 [b*S+s, h*128+d] ----
    float* stage = (float*)dsm;
#pragma unroll
    for (int p = 0; p < 2; p++) {
        if (p) __syncthreads();
#pragma unroll
        for (int mf = 0; mf < 4; mf++)
#pragma unroll
            for (int e = 0; e < 2; e++) {
                const int nf = 2 * p + e;
                const int row = mwb + mf * 16 + g;
                const int cm = (wid & 3) * 16 + e * 8 + ti * 2;
                *(float2*)&stage[row * STAGE_PITCH + cm] =
                    make_float2(ctx[mf][nf][0], ctx[mf][nf][1]);
                *(float2*)&stage[(row + 8) * STAGE_PITCH + cm] =
                    make_float2(ctx[mf][nf][2], ctx[mf][nf][3]);
            }
        __syncthreads();
#pragma unroll
        for (int it = 0; it < 8; it++) {
            const int lin = it * 1024 + tid * 4;
            const int row = lin >> 6;
            const int cm = lin & 63;
            const int col = ((cm >> 4) << 5) + (p << 4) + (cm & 15);
            float4 v = *(float4*)&stage[row * STAGE_PITCH + cm];
            size_t off = (size_t)(bb * S_DIM + m0 + row) * H_DIM + hh * HD_DIM + col;
            *(uint2*)(C16 + off) = make_uint2(pack_h2(v.x, v.y), pack_h2(v.z, v.w));
        }
    }
}

// ---------------------------------------------------------------------------
// LayerNorm
// ---------------------------------------------------------------------------
__device__ __forceinline__ float block_sum(float v)
{
    __shared__ float red[8];
#pragma unroll
    for (int o = 16; o; o >>= 1) v += __shfl_xor_sync(0xffffffffu, v, o);
    int w = threadIdx.x >> 5;
    if ((threadIdx.x & 31) == 0) red[w] = v;
    __syncthreads();
    float t = (threadIdx.x < 8) ? red[threadIdx.x] : 0.f;
    if (threadIdx.x < 32) {
#pragma unroll
        for (int o = 4; o; o >>= 1) t += __shfl_xor_sync(0xffffffffu, t, o);
        if (threadIdx.x == 0) red[0] = t;
    }
    __syncthreads();
    float r = red[0];
    __syncthreads();
    return r;
}

__global__ void ln_kernel(const float* __restrict__ D, const float* __restrict__ gamma,
                          const float* __restrict__ beta, const float* __restrict__ rsp,
                          float* __restrict__ out)
{
    int row = blockIdx.x;
    int tid = threadIdx.x;
    float rs = fminf(fmaxf(rsp[0], 0.f), 0.3f);

    const float* d = D + (size_t)row * H_DIM;
    float4 u0 = *(const float4*)(d + tid * 4);
    float4 u1 = *(const float4*)(d + 1024 + tid * 4);
    float x[8] = {rs*u0.x, rs*u0.y, rs*u0.z, rs*u0.w,
                  rs*u1.x, rs*u1.y, rs*u1.z, rs*u1.w};

    float ps = 0.f;
#pragma unroll
    for (int i = 0; i < 8; i++) ps += x[i];
    float mean = block_sum(ps) * (1.f / 2048.f);

    float pv = 0.f;
#pragma unroll
    for (int i = 0; i < 8; i++) { float dd = x[i] - mean; pv += dd * dd; }
    float var = block_sum(pv) * (1.f / 2048.f);
    float inv = rsqrtf(var + 1e-5f);

    float4 gz0 = *(const float4*)(gamma + tid * 4);
    float4 gz1 = *(const float4*)(gamma + 1024 + tid * 4);
    float4 bz0 = *(const float4*)(beta + tid * 4);
    float4 bz1 = *(const float4*)(beta + 1024 + tid * 4);

    float* o = out + (size_t)row * H_DIM;
    *(float4*)(o + tid * 4) = make_float4(
        (x[0]-mean)*inv*gz0.x + bz0.x, (x[1]-mean)*inv*gz0.y + bz0.y,
        (x[2]-mean)*inv*gz0.z + bz0.z, (x[3]-mean)*inv*gz0.w + bz0.w);
    *(float4*)(o + 1024 + tid * 4) = make_float4(
        (x[4]-mean)*inv*gz1.x + bz1.x, (x[5]-mean)*inv*gz1.y + bz1.y,
        (x[6]-mean)*inv*gz1.z + bz1.z, (x[7]-mean)*inv*gz1.w + bz1.w);
}

// ---------------------------------------------------------------------------
// Launch
// ---------------------------------------------------------------------------
extern "C" void kernel_launch(void* const* d_in, const int* in_sizes, int n_in,
                              void* d_out, int out_size)
{
    const float* hs    = (const float*)d_in[0];
    const float* at    = (const float*)d_in[1];
    const int*   mask  = (const int*)  d_in[2];
    const float* Wq    = (const float*)d_in[3];
    const float* bq    = (const float*)d_in[4];
    const float* Wk    = (const float*)d_in[5];
    const float* bk    = (const float*)d_in[6];
    const float* Wv    = (const float*)d_in[7];
    const float* bv    = (const float*)d_in[8];
    const float* Wo    = (const float*)d_in[9];
    const float* bo    = (const float*)d_in[10];
    const float* gamma = (const float*)d_in[11];
    const float* beta  = (const float*)d_in[12];
    const float* rsp   = (const float*)d_in[13];
    float* out = (float*)d_out;

    __half *hs16, *at16h, *at16l, *Wq16h, *Wq16l, *Wk16h, *Wk16l, *Wv16, *Wo16h, *Wo16l;
    __half *Q16, *K16h, *K16l, *Vt16h, *Vt16l, *C16;
    float *Db;
    cudaGetSymbolAddress((void**)&hs16,  g_hs16);
    cudaGetSymbolAddress((void**)&at16h, g_at16h); cudaGetSymbolAddress((void**)&at16l, g_at16l);
    cudaGetSymbolAddress((void**)&Wq16h, g_Wq16h); cudaGetSymbolAddress((void**)&Wq16l, g_Wq16l);
    cudaGetSymbolAddress((void**)&Wk16h, g_Wk16h); cudaGetSymbolAddress((void**)&Wk16l, g_Wk16l);
    cudaGetSymbolAddress((void**)&Wv16,  g_Wv16);
    cudaGetSymbolAddress((void**)&Wo16h, g_Wo16h); cudaGetSymbolAddress((void**)&Wo16l, g_Wo16l);
    cudaGetSymbolAddress((void**)&Q16,   g_Q16);
    cudaGetSymbolAddress((void**)&K16h,  g_K16h);  cudaGetSymbolAddress((void**)&K16l,  g_K16l);
    cudaGetSymbolAddress((void**)&Vt16h, g_Vt16h); cudaGetSymbolAddress((void**)&Vt16l, g_Vt16l);
    cudaGetSymbolAddress((void**)&C16,   g_C16);
    cudaGetSymbolAddress((void**)&Db,    g_D);

    cudaFuncSetAttribute(fused_attn_kernel,
                         cudaFuncAttributeMaxDynamicSharedMemorySize, AS_SMEM);

    // Pre-pass
    cast16_kernel<<<16384, 256>>>(hs, hs16);
    cast16_kernel<<<4096, 256>>>(Wv, Wv16);
    split16_kernel<<<2048, 256>>>(at, at16h, at16l);
    split16_kernel<<<4096, 256>>>(Wq, Wq16h, Wq16l);
    split16_kernel<<<4096, 256>>>(Wk, Wk16h, Wk16l);
    split16_kernel<<<4096, 256>>>(Wo, Wo16h, Wo16l);

    // Q projection -> fp16 single
    mma_gemm_f16<0><<<dim3(16, 64), 256>>>(hs16, Wq16h, Wq16l, bq,
                                           nullptr, Q16, nullptr, nullptr,
                                           2048, 2048, 2048, 2048);
    // K projection -> fp16 hi/lo
    mma_gemm_f16<1><<<dim3(16, 8), 256>>>(at16h, Wk16h, Wk16l, bk,
                                          nullptr, nullptr, K16h, K16l,
                                          2048, 2048, 2048, 2048);
    // V projection (A=Wv16, B=at hi/lo) -> Vt fp16 hi/lo [b,h,d,t]
    mma_gemm_f16<2><<<dim3(8, 16), 256>>>(Wv16, at16h, at16l, bv,
                                          nullptr, nullptr, Vt16h, Vt16l,
                                          2048, 2048, 2048, 0);
    // Fused scores + softmax + PV -> ctx fp16
    fused_attn_kernel<<<dim3(1, 16, 64), 256, AS_SMEM>>>(Q16, K16h, K16l,
                                                         Vt16h, Vt16l, mask, C16);
    // O projection -> fp32
    mma_gemm_f16<4><<<dim3(16, 64), 256>>>(C16, Wo16h, Wo16l, bo,
                                           Db, nullptr, nullptr, nullptr,
                                           2048, 2048, 2048, 2048);
    // residual scale + LayerNorm
    ln_kernel<<<8192, 256>>>(Db, gamma, beta, rsp, out);
}